// round 11
// baseline (speedup 1.0000x reference)
#include <cuda_runtime.h>
#include <cuda_fp16.h>
#include <cstdint>

#define N_USERC 100000
#define N_ITEMC 50000
#define NE      1600000
#define DU      128
#define DI      64
#define HH      256

#define AGG_BLK_ITEM ((N_ITEMC + 7) / 8)     // 6250
#define AGG_BLK_USER ((N_USERC + 7) / 8)     // 12500
#define MBLK_ITEM ((N_ITEMC + 127) / 128)    // 391
#define MBLK_USER ((N_USERC + 127) / 128)    // 782

// ---------------- device scratch ----------------
__device__ __align__(16) int g_cnt_item[N_ITEMC];
__device__ __align__(16) int g_cnt_user[N_USERC];
__device__ __align__(16) int g_cur_item[N_ITEMC];   // seeded with rs (write cursors)
__device__ __align__(16) int g_cur_user[N_USERC];
__device__ __align__(16) int g_rs_item[N_ITEMC + 1];
__device__ __align__(16) int g_rs_user[N_USERC + 1];
__device__ __align__(16) int g_col_ui[NE];
__device__ __align__(16) int g_col_iu[NE];

__device__ unsigned int g_tkt[2];
__device__ __align__(16) unsigned long long g_desc[2][160];

__device__ __align__(128) __half g_xu_h[(size_t)N_USERC * DU];
__device__ __align__(128) __half g_xi_h[(size_t)N_ITEMC * DI];
__device__ __align__(128) __half g_agg_item_h[(size_t)N_ITEMC * DU];
__device__ __align__(128) __half g_agg_user_h[(size_t)N_USERC * DI];
__device__ __align__(128) __half g_h_item_h[(size_t)N_ITEMC * HH];
__device__ __align__(128) __half g_h_user_h[(size_t)N_USERC * HH];
__device__ __align__(128) __half g_aggH_item_h[(size_t)N_ITEMC * HH];
__device__ __align__(128) __half g_aggH_user_h[(size_t)N_USERC * HH];
__device__ __align__(128) __half g_w_h[360448];

// weight offsets in g_w_h
#define O_W1L_UI 0
#define O_W1R_UI 32768
#define O_W1L_IU 49152
#define O_W1R_IU 65536
#define O_W2L_UI 98304
#define O_W2R_UI 163840
#define O_W2L_IU 229376
#define O_W2R_IU 294912

// ------- fp32 -> fp16 convert + degree count (fused; independent work) -------
struct CvtSeg { const float* s; __half* d; int n4; };
struct CvtArgs { CvtSeg seg[10]; const int* ui_dst; const int* iu_dst; };

__global__ void cvt_count_kernel(CvtArgs args) {
    const int gid = blockIdx.x * blockDim.x + threadIdx.x;
    const int stride = gridDim.x * blockDim.x;

    // degree count (latency-class; overlaps with convert's bandwidth work)
    for (int i = gid; i < NE / 4; i += stride) {
        int4 a = __ldg((const int4*)args.ui_dst + i);
        int4 b = __ldg((const int4*)args.iu_dst + i);
        atomicAdd(&g_cnt_item[a.x], 1); atomicAdd(&g_cnt_item[a.y], 1);
        atomicAdd(&g_cnt_item[a.z], 1); atomicAdd(&g_cnt_item[a.w], 1);
        atomicAdd(&g_cnt_user[b.x], 1); atomicAdd(&g_cnt_user[b.y], 1);
        atomicAdd(&g_cnt_user[b.z], 1); atomicAdd(&g_cnt_user[b.w], 1);
    }
#pragma unroll 1
    for (int k = 0; k < 10; k++) {
        CvtSeg g = args.seg[k];
        for (int i = gid; i < g.n4; i += stride) {
            float4 v = __ldg((const float4*)g.s + i);
            __half2 h0 = __float22half2_rn(make_float2(v.x, v.y));
            __half2 h1 = __float22half2_rn(make_float2(v.z, v.w));
            uint2 o;
            o.x = *(uint32_t*)&h0;
            o.y = *(uint32_t*)&h1;
            ((uint2*)g.d)[i] = o;
        }
    }
    // zero scan state (read only by the later scan kernel)
    for (int i = gid; i < 320; i += stride) ((unsigned long long*)g_desc)[i] = 0ull;
    if (gid == 0) { g_tkt[0] = 0u; g_tkt[1] = 0u; }
}

// ---------------- decoupled-lookback scan; seeds cur with rs ----------------
__global__ void scan_lookback_kernel() {
    const int y = blockIdx.y;
    const int* __restrict__ cnt = y == 0 ? g_cnt_item : g_cnt_user;
    int* __restrict__ rs  = y == 0 ? g_rs_item  : g_rs_user;
    int* __restrict__ cur = y == 0 ? g_cur_item : g_cur_user;
    const int n = y == 0 ? N_ITEMC : N_USERC;
    const int nblk = (n + 1023) / 1024;
    if (blockIdx.x >= nblk) return;

    __shared__ int s_vb;
    __shared__ int s_wsum[8];
    __shared__ int s_run;
    const int tid = threadIdx.x, lane = tid & 31, wid = tid >> 5;

    if (tid == 0) s_vb = atomicAdd(&g_tkt[y], 1u);
    __syncthreads();
    const int vb = s_vb;
    const int base = vb * 1024 + tid * 4;

    int v0 = 0, v1 = 0, v2 = 0, v3 = 0;
    if (base + 3 < n) {
        v0 = cnt[base]; v1 = cnt[base + 1]; v2 = cnt[base + 2]; v3 = cnt[base + 3];
    } else {
        if (base     < n) v0 = cnt[base];
        if (base + 1 < n) v1 = cnt[base + 1];
        if (base + 2 < n) v2 = cnt[base + 2];
        if (base + 3 < n) v3 = cnt[base + 3];
    }
    const int tot = v0 + v1 + v2 + v3;
    int inc = tot;
#pragma unroll
    for (int o = 1; o < 32; o <<= 1) {
        int u = __shfl_up_sync(0xffffffffu, inc, o);
        if (lane >= o) inc += u;
    }
    if (lane == 31) s_wsum[wid] = inc;
    __syncthreads();
    if (wid == 0) {
        int w = (lane < 8) ? s_wsum[lane] : 0;
#pragma unroll
        for (int o = 1; o < 8; o <<= 1) {
            int u = __shfl_up_sync(0xffffffffu, w, o);
            if (lane >= o) w += u;
        }
        if (lane < 8) s_wsum[lane] = w;
    }
    __syncthreads();
    const int agg = s_wsum[7];
    const int thr_exc = (wid ? s_wsum[wid - 1] : 0) + inc - tot;

    if (tid == 0) {
        if (vb == 0) {
            atomicExch(&g_desc[y][0], (2ull << 32) | (unsigned)agg);
            s_run = 0;
        } else {
            atomicExch(&g_desc[y][vb], (1ull << 32) | (unsigned)agg);
            int run = 0, p = vb - 1;
            while (true) {
                unsigned long long d;
                do { d = atomicAdd(&g_desc[y][p], 0ull); } while ((d >> 32) == 0ull);
                run += (int)(d & 0xffffffffull);
                if ((d >> 32) == 2ull) break;
                p--;
            }
            atomicExch(&g_desc[y][vb], (2ull << 32) | (unsigned)(run + agg));
            s_run = run;
        }
    }
    __syncthreads();
    const int run = s_run;
    const int e0 = run + thr_exc;
    // rs = exclusive scan; cur seeded with the same value (write cursor)
    if (base     < n) { int v = e0;                rs[base]     = v; cur[base]     = v; }
    if (base + 1 < n) { int v = e0 + v0;           rs[base + 1] = v; cur[base + 1] = v; }
    if (base + 2 < n) { int v = e0 + v0 + v1;      rs[base + 2] = v; cur[base + 2] = v; }
    if (base + 3 < n) { int v = e0 + v0 + v1 + v2; rs[base + 3] = v; cur[base + 3] = v; }
    if (vb == nblk - 1 && tid == 0) rs[n] = run + agg;
}

// fill: single atomic per edge (cursor pre-seeded with row start)
__global__ void fill_kernel(const int* __restrict__ ui_src, const int* __restrict__ ui_dst,
                            const int* __restrict__ iu_src, const int* __restrict__ iu_dst) {
    int i = blockIdx.x * blockDim.x + threadIdx.x;
    if (i >= NE / 4) return;
    int4 us = __ldg((const int4*)ui_src + i);
    int4 ud = __ldg((const int4*)ui_dst + i);
    int4 is = __ldg((const int4*)iu_src + i);
    int4 id = __ldg((const int4*)iu_dst + i);
    {
        int p0 = atomicAdd(&g_cur_item[ud.x], 1);
        int p1 = atomicAdd(&g_cur_item[ud.y], 1);
        int p2 = atomicAdd(&g_cur_item[ud.z], 1);
        int p3 = atomicAdd(&g_cur_item[ud.w], 1);
        g_col_ui[p0] = us.x;
        g_col_ui[p1] = us.y;
        g_col_ui[p2] = us.z;
        g_col_ui[p3] = us.w;
    }
    {
        int p0 = atomicAdd(&g_cur_user[id.x], 1);
        int p1 = atomicAdd(&g_cur_user[id.y], 1);
        int p2 = atomicAdd(&g_cur_user[id.z], 1);
        int p3 = atomicAdd(&g_cur_user[id.w], 1);
        g_col_iu[p0] = is.x;
        g_col_iu[p1] = is.y;
        g_col_iu[p2] = is.z;
        g_col_iu[p3] = is.w;
    }
}

// ---------------- fp16 gather-based segment mean ----------------
template <int HV>
__device__ __forceinline__ void ld_row(const __half* p, int lane, uint32_t* raw) {
    if constexpr (HV == 4) {
        uint4 t = __ldg((const uint4*)p + lane);
        raw[0] = t.x; raw[1] = t.y; raw[2] = t.z; raw[3] = t.w;
    } else if constexpr (HV == 2) {
        uint2 t = __ldg((const uint2*)p + lane);
        raw[0] = t.x; raw[1] = t.y;
    } else {
        raw[0] = __ldg((const uint32_t*)p + lane);
    }
}

template <int HV>
__device__ __forceinline__ void agg_body_h(const __half* __restrict__ X,
                                           const int* __restrict__ rs,
                                           const int* __restrict__ col,
                                           __half* __restrict__ out, int w, int lane) {
    const int F = HV * 64;
    int s = rs[w], e = rs[w + 1];
    float2 acc[4][HV];
#pragma unroll
    for (int u = 0; u < 4; u++)
#pragma unroll
        for (int v = 0; v < HV; v++) acc[u][v] = make_float2(0.f, 0.f);

    int j = s;
    for (; j + 3 < e; j += 4) {
        uint32_t raw[4][HV];
#pragma unroll
        for (int u = 0; u < 4; u++)
            ld_row<HV>(X + (size_t)col[j + u] * F, lane, raw[u]);
#pragma unroll
        for (int u = 0; u < 4; u++)
#pragma unroll
            for (int v = 0; v < HV; v++) {
                float2 f = __half22float2(*(__half2*)&raw[u][v]);
                acc[u][v].x += f.x; acc[u][v].y += f.y;
            }
    }
    for (; j < e; j++) {
        uint32_t raw[HV];
        ld_row<HV>(X + (size_t)col[j] * F, lane, raw);
#pragma unroll
        for (int v = 0; v < HV; v++) {
            float2 f = __half22float2(*(__half2*)&raw[v]);
            acc[0][v].x += f.x; acc[0][v].y += f.y;
        }
    }
    float inv = (e > s) ? 1.0f / (float)(e - s) : 0.0f;
    uint32_t o[HV];
#pragma unroll
    for (int v = 0; v < HV; v++) {
        float2 m;
        m.x = (acc[0][v].x + acc[1][v].x + acc[2][v].x + acc[3][v].x) * inv;
        m.y = (acc[0][v].y + acc[1][v].y + acc[2][v].y + acc[3][v].y) * inv;
        __half2 h = __float22half2_rn(m);
        o[v] = *(uint32_t*)&h;
    }
    __half* orow = out + (size_t)w * F;
    if constexpr (HV == 4) ((uint4*)orow)[lane] = make_uint4(o[0], o[1], o[2], o[3]);
    else if constexpr (HV == 2) ((uint2*)orow)[lane] = make_uint2(o[0], o[1]);
    else ((uint32_t*)orow)[lane] = o[0];
}

__global__ __launch_bounds__(256) void agg_l1_kernel() {
    const int gb = blockIdx.x;
    const int lane = threadIdx.x & 31;
    const int wl = threadIdx.x >> 5;
    if (gb < AGG_BLK_ITEM) {
        int w = gb * 8 + wl;
        if (w < N_ITEMC) agg_body_h<2>(g_xu_h, g_rs_item, g_col_ui, g_agg_item_h, w, lane);
    } else {
        int w = (gb - AGG_BLK_ITEM) * 8 + wl;
        if (w < N_USERC) agg_body_h<1>(g_xi_h, g_rs_user, g_col_iu, g_agg_user_h, w, lane);
    }
}

__global__ __launch_bounds__(256) void agg_l2_kernel() {
    const int gb = blockIdx.x;
    const int lane = threadIdx.x & 31;
    const int wl = threadIdx.x >> 5;
    if (gb < AGG_BLK_ITEM) {
        int w = gb * 8 + wl;
        if (w < N_ITEMC) agg_body_h<4>(g_h_user_h, g_rs_item, g_col_ui, g_aggH_item_h, w, lane);
    } else {
        int w = (gb - AGG_BLK_ITEM) * 8 + wl;
        if (w < N_USERC) agg_body_h<4>(g_h_item_h, g_rs_user, g_col_iu, g_aggH_user_h, w, lane);
    }
}

// ================= fp16 mma.sync dual-A GEMM, cp.async 3-stage =================
#define HROW_B    80
#define HSTAGE_A  (128 * HROW_B)           // 10240
#define HSTAGE    (2 * HSTAGE_A)           // 20480
#define NSTAGE    3
#define HGEMM_SMEM (NSTAGE * HSTAGE)       // 61440

struct GemmSideH {
    const __half *A1, *W1, *A2, *W2;
    const float* bias;
    void* C;
    int K1, K2, M;
};

__device__ __forceinline__ uint32_t smem_u32(const void* p) {
    uint32_t a;
    asm("{ .reg .u64 t; cvta.to.shared.u64 t, %1; cvt.u32.u64 %0, t; }" : "=r"(a) : "l"(p));
    return a;
}

__device__ __forceinline__ void ldsm_x4(uint32_t* r, uint32_t addr) {
    asm volatile("ldmatrix.sync.aligned.m8n8.x4.shared.b16 {%0,%1,%2,%3}, [%4];"
                 : "=r"(r[0]), "=r"(r[1]), "=r"(r[2]), "=r"(r[3]) : "r"(addr));
}

__device__ __forceinline__ void mma_f16(float* d, const uint32_t* a, uint32_t b0, uint32_t b1) {
    asm volatile(
        "mma.sync.aligned.m16n8k16.row.col.f32.f16.f16.f32 "
        "{%0,%1,%2,%3}, {%4,%5,%6,%7}, {%8,%9}, {%0,%1,%2,%3};"
        : "+f"(d[0]), "+f"(d[1]), "+f"(d[2]), "+f"(d[3])
        : "r"(a[0]), "r"(a[1]), "r"(a[2]), "r"(a[3]), "r"(b0), "r"(b1));
}

__device__ __forceinline__ void cp_async16(uint32_t smem, const void* g, bool pred) {
    int sz = pred ? 16 : 0;
    asm volatile("cp.async.cg.shared.global [%0], [%1], 16, %2;"
                 :: "r"(smem), "l"(g), "r"(sz) : "memory");
}
#define CP_COMMIT() asm volatile("cp.async.commit_group;" ::: "memory")
#define CP_WAIT1()  asm volatile("cp.async.wait_group 1;" ::: "memory")

template <bool RELU, typename CT>
__global__ __launch_bounds__(256, 2) void gemm_h_fused(GemmSideH sa, GemmSideH sb, int mblk_a) {
    extern __shared__ __align__(16) char dsmem[];
    const uint32_t sm0 = smem_u32(dsmem);

    const bool sideA = (int)blockIdx.x < mblk_a;
    const __half* A1 = sideA ? sa.A1 : sb.A1;
    const __half* W1 = sideA ? sa.W1 : sb.W1;
    const __half* A2 = sideA ? sa.A2 : sb.A2;
    const __half* W2 = sideA ? sa.W2 : sb.W2;
    const float* bias = sideA ? sa.bias : sb.bias;
    CT* C = (CT*)(sideA ? sa.C : sb.C);
    const int K1 = sideA ? sa.K1 : sb.K1;
    const int K2 = sideA ? sa.K2 : sb.K2;
    const int M  = sideA ? sa.M  : sb.M;
    const int mb = sideA ? blockIdx.x : blockIdx.x - mblk_a;

    const int tid = threadIdx.x;
    const int wid = tid >> 5;
    const int lane = tid & 31;
    const int warp_m = wid >> 2;
    const int warp_n = wid & 3;
    const int m0 = mb * 128;
    const int n0 = blockIdx.y * 128;

    const int row0 = tid >> 2;
    const int cc8 = (tid & 3) * 8;
    const uint32_t stoff = (uint32_t)(row0 * HROW_B + (tid & 3) * 16);

    float acc[4][4][4];
#pragma unroll
    for (int i = 0; i < 4; i++)
#pragma unroll
        for (int j = 0; j < 4; j++)
#pragma unroll
            for (int k = 0; k < 4; k++) acc[i][j][k] = 0.f;

    const int n1 = K1 / 32;
    const int n2 = K2 / 32;
    const int T = n1 + n2;

    auto issue_g = [&](int it, int slot) {
        const __half* A; const __half* W; int K, k0;
        if (it < n1) { A = A1; W = W1; K = K1; k0 = it * 32; }
        else         { A = A2; W = W2; K = K2; k0 = (it - n1) * 32; }
        const int cc = k0 + cc8;
        const uint32_t bA = sm0 + slot * HSTAGE;
        const uint32_t bB = bA + HSTAGE_A;
#pragma unroll
        for (int q = 0; q < 2; q++) {
            const int r = row0 + 64 * q;
            cp_async16(bA + stoff + (uint32_t)(64 * q * HROW_B),
                       A + (size_t)(m0 + r) * K + cc, m0 + r < M);
            cp_async16(bB + stoff + (uint32_t)(64 * q * HROW_B),
                       W + (size_t)(n0 + r) * K + cc, true);
        }
    };

    const int rowsel = (lane & 7) | (((lane >> 3) & 1) << 3);
    const int colsel = (lane >> 4) * 16;

    auto compute_s = [&](int st) {
        const uint32_t bA = sm0 + st * HSTAGE;
        const uint32_t bB = bA + HSTAGE_A;
        const uint32_t aBase = bA + (uint32_t)((warp_m * 64 + rowsel) * HROW_B + colsel);
        const uint32_t bBase = bB + (uint32_t)((warp_n * 32 + rowsel) * HROW_B + colsel);
#pragma unroll
        for (int ks = 0; ks < 2; ks++) {
            const uint32_t ko = ks * 32;
            uint32_t af[4][4], bf[8];
#pragma unroll
            for (int i = 0; i < 4; i++)
                ldsm_x4(af[i], aBase + i * (16 * HROW_B) + ko);
            ldsm_x4(bf + 0, bBase + ko);
            ldsm_x4(bf + 4, bBase + 16 * HROW_B + ko);
#pragma unroll
            for (int i = 0; i < 4; i++)
#pragma unroll
                for (int j = 0; j < 4; j++) {
                    const int bi = (j >> 1) * 4 + (j & 1);
                    mma_f16(acc[i][j], af[i], bf[bi], bf[bi + 2]);
                }
        }
    };

    issue_g(0, 0);
    CP_COMMIT();
    if (T > 1) issue_g(1, 1);
    CP_COMMIT();
    CP_WAIT1();
    __syncthreads();

    int slot = 0;
#pragma unroll 1
    for (int it = 0; it < T; it++) {
        compute_s(slot);
        if (it + 2 < T) issue_g(it + 2, (it + 2) % NSTAGE);
        CP_COMMIT();
        CP_WAIT1();
        __syncthreads();
        slot = (slot + 1 == NSTAGE) ? 0 : slot + 1;
    }

    const int g = lane >> 2;
    const int t = lane & 3;
#pragma unroll
    for (int j = 0; j < 4; j++) {
        const int nb = n0 + warp_n * 32 + j * 8 + t * 2;
        const float bx = bias[nb], by = bias[nb + 1];
#pragma unroll
        for (int i = 0; i < 4; i++) {
            const int rlo = m0 + warp_m * 64 + i * 16 + g;
            if (rlo < M) {
                float vx = acc[i][j][0] + bx, vy = acc[i][j][1] + by;
                if (RELU) { vx = fmaxf(vx, 0.f); vy = fmaxf(vy, 0.f); }
                if constexpr (sizeof(CT) == 2) {
                    __half2 hv = __float22half2_rn(make_float2(vx, vy));
                    *(__half2*)((__half*)C + (size_t)rlo * HH + nb) = hv;
                } else {
                    *(float2*)((float*)C + (size_t)rlo * HH + nb) = make_float2(vx, vy);
                }
            }
            const int rhi = rlo + 8;
            if (rhi < M) {
                float vx = acc[i][j][2] + bx, vy = acc[i][j][3] + by;
                if (RELU) { vx = fmaxf(vx, 0.f); vy = fmaxf(vy, 0.f); }
                if constexpr (sizeof(CT) == 2) {
                    __half2 hv = __float22half2_rn(make_float2(vx, vy));
                    *(__half2*)((__half*)C + (size_t)rhi * HH + nb) = hv;
                } else {
                    *(float2*)((float*)C + (size_t)rhi * HH + nb) = make_float2(vx, vy);
                }
            }
        }
    }
}

// ---------------- host ----------------
extern "C" void kernel_launch(void* const* d_in, const int* in_sizes, int n_in,
                              void* d_out, int out_size) {
    const float* x_user = (const float*)d_in[0];
    const float* x_item = (const float*)d_in[1];
    const int* ui_src = (const int*)d_in[2];
    const int* ui_dst = (const int*)d_in[3];
    const int* iu_src = (const int*)d_in[4];
    const int* iu_dst = (const int*)d_in[5];
    const float* W1l_ui = (const float*)d_in[6];
    const float* b1_ui  = (const float*)d_in[7];
    const float* W1r_ui = (const float*)d_in[8];
    const float* W1l_iu = (const float*)d_in[9];
    const float* b1_iu  = (const float*)d_in[10];
    const float* W1r_iu = (const float*)d_in[11];
    const float* W2l_ui = (const float*)d_in[12];
    const float* b2_ui  = (const float*)d_in[13];
    const float* W2r_ui = (const float*)d_in[14];
    const float* W2l_iu = (const float*)d_in[15];
    const float* b2_iu  = (const float*)d_in[16];
    const float* W2r_iu = (const float*)d_in[17];

    int *cnt_item, *cnt_user;
    __half *xu_h, *xi_h, *agg_item_h, *agg_user_h, *h_item_h, *h_user_h,
           *aggH_item_h, *aggH_user_h, *w_h;
    cudaGetSymbolAddress((void**)&cnt_item, g_cnt_item);
    cudaGetSymbolAddress((void**)&cnt_user, g_cnt_user);
    cudaGetSymbolAddress((void**)&xu_h, g_xu_h);
    cudaGetSymbolAddress((void**)&xi_h, g_xi_h);
    cudaGetSymbolAddress((void**)&agg_item_h, g_agg_item_h);
    cudaGetSymbolAddress((void**)&agg_user_h, g_agg_user_h);
    cudaGetSymbolAddress((void**)&h_item_h, g_h_item_h);
    cudaGetSymbolAddress((void**)&h_user_h, g_h_user_h);
    cudaGetSymbolAddress((void**)&aggH_item_h, g_aggH_item_h);
    cudaGetSymbolAddress((void**)&aggH_user_h, g_aggH_user_h);
    cudaGetSymbolAddress((void**)&w_h, g_w_h);

    cudaFuncSetAttribute(gemm_h_fused<true, __half>,
                         cudaFuncAttributeMaxDynamicSharedMemorySize, HGEMM_SMEM);
    cudaFuncSetAttribute(gemm_h_fused<false, float>,
                         cudaFuncAttributeMaxDynamicSharedMemorySize, HGEMM_SMEM);

    // cnt must be zero BEFORE cvt_count (which counts into it)
    cudaMemsetAsync(cnt_item, 0, N_ITEMC * sizeof(int), 0);
    cudaMemsetAsync(cnt_user, 0, N_USERC * sizeof(int), 0);

    // fp32 -> fp16 convert + degree count + scan-state zeroing (one launch)
    {
        CvtArgs a;
        a.seg[0] = { x_user, xu_h, (N_USERC * DU) / 4 };
        a.seg[1] = { x_item, xi_h, (N_ITEMC * DI) / 4 };
        a.seg[2] = { W1l_ui, w_h + O_W1L_UI, (HH * DU) / 4 };
        a.seg[3] = { W1r_ui, w_h + O_W1R_UI, (HH * DI) / 4 };
        a.seg[4] = { W1l_iu, w_h + O_W1L_IU, (HH * DI) / 4 };
        a.seg[5] = { W1r_iu, w_h + O_W1R_IU, (HH * DU) / 4 };
        a.seg[6] = { W2l_ui, w_h + O_W2L_UI, (HH * HH) / 4 };
        a.seg[7] = { W2r_ui, w_h + O_W2R_UI, (HH * HH) / 4 };
        a.seg[8] = { W2l_iu, w_h + O_W2L_IU, (HH * HH) / 4 };
        a.seg[9] = { W2r_iu, w_h + O_W2R_IU, (HH * HH) / 4 };
        a.ui_dst = ui_dst;
        a.iu_dst = iu_dst;
        cvt_count_kernel<<<1024, 256>>>(a);
    }

    // scan (seeds cur with rs), then fill (single atomic per edge)
    scan_lookback_kernel<<<dim3(98, 2), 256>>>();
    fill_kernel<<<(NE / 4 + 255) / 256, 256>>>(ui_src, ui_dst, iu_src, iu_dst);

    // layer 1 aggregation
    agg_l1_kernel<<<AGG_BLK_ITEM + AGG_BLK_USER, 256>>>();

    // layer 1 fused GEMMs (fp16 in, fp16 out + relu)
    {
        GemmSideH si = { agg_item_h, w_h + O_W1L_UI, xi_h, w_h + O_W1R_UI,
                         b1_ui, h_item_h, DU, DI, N_ITEMC };
        GemmSideH su = { agg_user_h, w_h + O_W1L_IU, xu_h, w_h + O_W1R_IU,
                         b1_iu, h_user_h, DI, DU, N_USERC };
        gemm_h_fused<true, __half><<<dim3(MBLK_ITEM + MBLK_USER, 2), 256, HGEMM_SMEM>>>(
            si, su, MBLK_ITEM);
    }

    // layer 2 aggregation
    agg_l2_kernel<<<AGG_BLK_ITEM + AGG_BLK_USER, 256>>>();

    // layer 2 fused GEMMs (fp16 in, fp32 out)
    float* out_user = (float*)d_out;
    float* out_item = out_user + (size_t)N_USERC * HH;
    {
        GemmSideH si = { aggH_item_h, w_h + O_W2L_UI, h_item_h, w_h + O_W2R_UI,
                         b2_ui, out_item, HH, HH, N_ITEMC };
        GemmSideH su = { aggH_user_h, w_h + O_W2L_IU, h_user_h, w_h + O_W2R_IU,
                         b2_iu, out_user, HH, HH, N_USERC };
        gemm_h_fused<false, float><<<dim3(MBLK_ITEM + MBLK_USER, 2), 256, HGEMM_SMEM>>>(
            si, su, MBLK_ITEM);
    }
}

// round 12
// speedup vs baseline: 1.4081x; 1.4081x over previous
#include <cuda_runtime.h>
#include <cuda_fp16.h>
#include <cstdint>

#define N_USERC 100000
#define N_ITEMC 50000
#define NE      1600000
#define DU      128
#define DI      64
#define HH      256

#define AGG_BLK_ITEM ((N_ITEMC + 7) / 8)     // 6250
#define AGG_BLK_USER ((N_USERC + 7) / 8)     // 12500
#define MBLK_ITEM ((N_ITEMC + 127) / 128)    // 391
#define MBLK_USER ((N_USERC + 127) / 128)    // 782

// ---------------- device scratch ----------------
__device__ __align__(16) int g_cnt_item[N_ITEMC];
__device__ __align__(16) int g_cnt_user[N_USERC];
__device__ __align__(16) int g_cur_item[N_ITEMC];   // seeded with rs (write cursors)
__device__ __align__(16) int g_cur_user[N_USERC];
__device__ __align__(16) int g_rs_item[N_ITEMC + 1];
__device__ __align__(16) int g_rs_user[N_USERC + 1];
__device__ __align__(16) int g_col_ui[NE];
__device__ __align__(16) int g_col_iu[NE];

__device__ unsigned int g_tkt[2];
__device__ __align__(16) unsigned long long g_desc[2][160];

__device__ __align__(128) __half g_xu_h[(size_t)N_USERC * DU];
__device__ __align__(128) __half g_xi_h[(size_t)N_ITEMC * DI];
__device__ __align__(128) __half g_agg_item_h[(size_t)N_ITEMC * DU];
__device__ __align__(128) __half g_agg_user_h[(size_t)N_USERC * DI];
__device__ __align__(128) __half g_h_item_h[(size_t)N_ITEMC * HH];
__device__ __align__(128) __half g_h_user_h[(size_t)N_USERC * HH];
__device__ __align__(128) __half g_aggH_item_h[(size_t)N_ITEMC * HH];
__device__ __align__(128) __half g_aggH_user_h[(size_t)N_USERC * HH];
__device__ __align__(128) __half g_w_h[360448];

// weight offsets in g_w_h
#define O_W1L_UI 0
#define O_W1R_UI 32768
#define O_W1L_IU 49152
#define O_W1R_IU 65536
#define O_W2L_UI 98304
#define O_W2R_UI 163840
#define O_W2L_IU 229376
#define O_W2R_IU 294912

// ---------------- fp32 -> fp16 convert + scratch zeroing (R10 structure) ----------------
struct CvtSeg { const float* s; __half* d; int n4; };
struct CvtArgs { CvtSeg seg[10]; };

__global__ void cvt_kernel(CvtArgs args) {
    const int gid = blockIdx.x * blockDim.x + threadIdx.x;
    const int stride = gridDim.x * blockDim.x;
#pragma unroll 1
    for (int k = 0; k < 10; k++) {
        CvtSeg g = args.seg[k];
        for (int i = gid; i < g.n4; i += stride) {
            float4 v = __ldg((const float4*)g.s + i);
            __half2 h0 = __float22half2_rn(make_float2(v.x, v.y));
            __half2 h1 = __float22half2_rn(make_float2(v.z, v.w));
            uint2 o;
            o.x = *(uint32_t*)&h0;
            o.y = *(uint32_t*)&h1;
            ((uint2*)g.d)[i] = o;
        }
    }
    // zero counters / scan state (replaces memsets)
    for (int i = gid; i < N_ITEMC / 4; i += stride) ((int4*)g_cnt_item)[i] = make_int4(0, 0, 0, 0);
    for (int i = gid; i < N_USERC / 4; i += stride) ((int4*)g_cnt_user)[i] = make_int4(0, 0, 0, 0);
    for (int i = gid; i < 320; i += stride) ((unsigned long long*)g_desc)[i] = 0ull;
    if (gid == 0) { g_tkt[0] = 0u; g_tkt[1] = 0u; }
}

// ---------------- CSR build (4 edges / thread for MLP) ----------------
__global__ void count_kernel(const int* __restrict__ ui_dst, const int* __restrict__ iu_dst) {
    int i = blockIdx.x * blockDim.x + threadIdx.x;
    if (i >= NE / 4) return;
    int4 a = __ldg((const int4*)ui_dst + i);
    int4 b = __ldg((const int4*)iu_dst + i);
    atomicAdd(&g_cnt_item[a.x], 1); atomicAdd(&g_cnt_item[a.y], 1);
    atomicAdd(&g_cnt_item[a.z], 1); atomicAdd(&g_cnt_item[a.w], 1);
    atomicAdd(&g_cnt_user[b.x], 1); atomicAdd(&g_cnt_user[b.y], 1);
    atomicAdd(&g_cnt_user[b.z], 1); atomicAdd(&g_cnt_user[b.w], 1);
}

// ---------------- decoupled-lookback scan; seeds cur with rs ----------------
__global__ void scan_lookback_kernel() {
    const int y = blockIdx.y;
    const int* __restrict__ cnt = y == 0 ? g_cnt_item : g_cnt_user;
    int* __restrict__ rs  = y == 0 ? g_rs_item  : g_rs_user;
    int* __restrict__ cur = y == 0 ? g_cur_item : g_cur_user;
    const int n = y == 0 ? N_ITEMC : N_USERC;
    const int nblk = (n + 1023) / 1024;
    if (blockIdx.x >= nblk) return;

    __shared__ int s_vb;
    __shared__ int s_wsum[8];
    __shared__ int s_run;
    const int tid = threadIdx.x, lane = tid & 31, wid = tid >> 5;

    if (tid == 0) s_vb = atomicAdd(&g_tkt[y], 1u);
    __syncthreads();
    const int vb = s_vb;
    const int base = vb * 1024 + tid * 4;

    int v0 = 0, v1 = 0, v2 = 0, v3 = 0;
    if (base + 3 < n) {
        v0 = cnt[base]; v1 = cnt[base + 1]; v2 = cnt[base + 2]; v3 = cnt[base + 3];
    } else {
        if (base     < n) v0 = cnt[base];
        if (base + 1 < n) v1 = cnt[base + 1];
        if (base + 2 < n) v2 = cnt[base + 2];
        if (base + 3 < n) v3 = cnt[base + 3];
    }
    const int tot = v0 + v1 + v2 + v3;
    int inc = tot;
#pragma unroll
    for (int o = 1; o < 32; o <<= 1) {
        int u = __shfl_up_sync(0xffffffffu, inc, o);
        if (lane >= o) inc += u;
    }
    if (lane == 31) s_wsum[wid] = inc;
    __syncthreads();
    if (wid == 0) {
        int w = (lane < 8) ? s_wsum[lane] : 0;
#pragma unroll
        for (int o = 1; o < 8; o <<= 1) {
            int u = __shfl_up_sync(0xffffffffu, w, o);
            if (lane >= o) w += u;
        }
        if (lane < 8) s_wsum[lane] = w;
    }
    __syncthreads();
    const int agg = s_wsum[7];
    const int thr_exc = (wid ? s_wsum[wid - 1] : 0) + inc - tot;

    if (tid == 0) {
        if (vb == 0) {
            atomicExch(&g_desc[y][0], (2ull << 32) | (unsigned)agg);
            s_run = 0;
        } else {
            atomicExch(&g_desc[y][vb], (1ull << 32) | (unsigned)agg);
            int run = 0, p = vb - 1;
            while (true) {
                unsigned long long d;
                do { d = atomicAdd(&g_desc[y][p], 0ull); } while ((d >> 32) == 0ull);
                run += (int)(d & 0xffffffffull);
                if ((d >> 32) == 2ull) break;
                p--;
            }
            atomicExch(&g_desc[y][vb], (2ull << 32) | (unsigned)(run + agg));
            s_run = run;
        }
    }
    __syncthreads();
    const int run = s_run;
    const int e0 = run + thr_exc;
    // rs = exclusive scan; cur seeded with the same value (write cursor)
    if (base     < n) { int v = e0;                rs[base]     = v; cur[base]     = v; }
    if (base + 1 < n) { int v = e0 + v0;           rs[base + 1] = v; cur[base + 1] = v; }
    if (base + 2 < n) { int v = e0 + v0 + v1;      rs[base + 2] = v; cur[base + 2] = v; }
    if (base + 3 < n) { int v = e0 + v0 + v1 + v2; rs[base + 3] = v; cur[base + 3] = v; }
    if (vb == nblk - 1 && tid == 0) rs[n] = run + agg;
}

// fill: single atomic per edge (cursor pre-seeded with row start; no rs load)
__global__ void fill_kernel(const int* __restrict__ ui_src, const int* __restrict__ ui_dst,
                            const int* __restrict__ iu_src, const int* __restrict__ iu_dst) {
    int i = blockIdx.x * blockDim.x + threadIdx.x;
    if (i >= NE / 4) return;
    int4 us = __ldg((const int4*)ui_src + i);
    int4 ud = __ldg((const int4*)ui_dst + i);
    int4 is = __ldg((const int4*)iu_src + i);
    int4 id = __ldg((const int4*)iu_dst + i);
    {
        int p0 = atomicAdd(&g_cur_item[ud.x], 1);
        int p1 = atomicAdd(&g_cur_item[ud.y], 1);
        int p2 = atomicAdd(&g_cur_item[ud.z], 1);
        int p3 = atomicAdd(&g_cur_item[ud.w], 1);
        g_col_ui[p0] = us.x;
        g_col_ui[p1] = us.y;
        g_col_ui[p2] = us.z;
        g_col_ui[p3] = us.w;
    }
    {
        int p0 = atomicAdd(&g_cur_user[id.x], 1);
        int p1 = atomicAdd(&g_cur_user[id.y], 1);
        int p2 = atomicAdd(&g_cur_user[id.z], 1);
        int p3 = atomicAdd(&g_cur_user[id.w], 1);
        g_col_iu[p0] = is.x;
        g_col_iu[p1] = is.y;
        g_col_iu[p2] = is.z;
        g_col_iu[p3] = is.w;
    }
}

// ---------------- fp16 gather-based segment mean ----------------
template <int HV>
__device__ __forceinline__ void ld_row(const __half* p, int lane, uint32_t* raw) {
    if constexpr (HV == 4) {
        uint4 t = __ldg((const uint4*)p + lane);
        raw[0] = t.x; raw[1] = t.y; raw[2] = t.z; raw[3] = t.w;
    } else if constexpr (HV == 2) {
        uint2 t = __ldg((const uint2*)p + lane);
        raw[0] = t.x; raw[1] = t.y;
    } else {
        raw[0] = __ldg((const uint32_t*)p + lane);
    }
}

template <int HV>
__device__ __forceinline__ void agg_body_h(const __half* __restrict__ X,
                                           const int* __restrict__ rs,
                                           const int* __restrict__ col,
                                           __half* __restrict__ out, int w, int lane) {
    const int F = HV * 64;
    int s = rs[w], e = rs[w + 1];
    float2 acc[4][HV];
#pragma unroll
    for (int u = 0; u < 4; u++)
#pragma unroll
        for (int v = 0; v < HV; v++) acc[u][v] = make_float2(0.f, 0.f);

    int j = s;
    for (; j + 3 < e; j += 4) {
        uint32_t raw[4][HV];
#pragma unroll
        for (int u = 0; u < 4; u++)
            ld_row<HV>(X + (size_t)col[j + u] * F, lane, raw[u]);
#pragma unroll
        for (int u = 0; u < 4; u++)
#pragma unroll
            for (int v = 0; v < HV; v++) {
                float2 f = __half22float2(*(__half2*)&raw[u][v]);
                acc[u][v].x += f.x; acc[u][v].y += f.y;
            }
    }
    for (; j < e; j++) {
        uint32_t raw[HV];
        ld_row<HV>(X + (size_t)col[j] * F, lane, raw);
#pragma unroll
        for (int v = 0; v < HV; v++) {
            float2 f = __half22float2(*(__half2*)&raw[v]);
            acc[0][v].x += f.x; acc[0][v].y += f.y;
        }
    }
    float inv = (e > s) ? 1.0f / (float)(e - s) : 0.0f;
    uint32_t o[HV];
#pragma unroll
    for (int v = 0; v < HV; v++) {
        float2 m;
        m.x = (acc[0][v].x + acc[1][v].x + acc[2][v].x + acc[3][v].x) * inv;
        m.y = (acc[0][v].y + acc[1][v].y + acc[2][v].y + acc[3][v].y) * inv;
        __half2 h = __float22half2_rn(m);
        o[v] = *(uint32_t*)&h;
    }
    __half* orow = out + (size_t)w * F;
    if constexpr (HV == 4) ((uint4*)orow)[lane] = make_uint4(o[0], o[1], o[2], o[3]);
    else if constexpr (HV == 2) ((uint2*)orow)[lane] = make_uint2(o[0], o[1]);
    else ((uint32_t*)orow)[lane] = o[0];
}

__global__ __launch_bounds__(256) void agg_l1_kernel() {
    const int gb = blockIdx.x;
    const int lane = threadIdx.x & 31;
    const int wl = threadIdx.x >> 5;
    if (gb < AGG_BLK_ITEM) {
        int w = gb * 8 + wl;
        if (w < N_ITEMC) agg_body_h<2>(g_xu_h, g_rs_item, g_col_ui, g_agg_item_h, w, lane);
    } else {
        int w = (gb - AGG_BLK_ITEM) * 8 + wl;
        if (w < N_USERC) agg_body_h<1>(g_xi_h, g_rs_user, g_col_iu, g_agg_user_h, w, lane);
    }
}

__global__ __launch_bounds__(256) void agg_l2_kernel() {
    const int gb = blockIdx.x;
    const int lane = threadIdx.x & 31;
    const int wl = threadIdx.x >> 5;
    if (gb < AGG_BLK_ITEM) {
        int w = gb * 8 + wl;
        if (w < N_ITEMC) agg_body_h<4>(g_h_user_h, g_rs_item, g_col_ui, g_aggH_item_h, w, lane);
    } else {
        int w = (gb - AGG_BLK_ITEM) * 8 + wl;
        if (w < N_USERC) agg_body_h<4>(g_h_item_h, g_rs_user, g_col_iu, g_aggH_user_h, w, lane);
    }
}

// ================= fp16 mma.sync dual-A GEMM, cp.async 3-stage =================
#define HROW_B    80
#define HSTAGE_A  (128 * HROW_B)           // 10240
#define HSTAGE    (2 * HSTAGE_A)           // 20480
#define NSTAGE    3
#define HGEMM_SMEM (NSTAGE * HSTAGE)       // 61440

struct GemmSideH {
    const __half *A1, *W1, *A2, *W2;
    const float* bias;
    void* C;
    int K1, K2, M;
};

__device__ __forceinline__ uint32_t smem_u32(const void* p) {
    uint32_t a;
    asm("{ .reg .u64 t; cvta.to.shared.u64 t, %1; cvt.u32.u64 %0, t; }" : "=r"(a) : "l"(p));
    return a;
}

__device__ __forceinline__ void ldsm_x4(uint32_t* r, uint32_t addr) {
    asm volatile("ldmatrix.sync.aligned.m8n8.x4.shared.b16 {%0,%1,%2,%3}, [%4];"
                 : "=r"(r[0]), "=r"(r[1]), "=r"(r[2]), "=r"(r[3]) : "r"(addr));
}

__device__ __forceinline__ void mma_f16(float* d, const uint32_t* a, uint32_t b0, uint32_t b1) {
    asm volatile(
        "mma.sync.aligned.m16n8k16.row.col.f32.f16.f16.f32 "
        "{%0,%1,%2,%3}, {%4,%5,%6,%7}, {%8,%9}, {%0,%1,%2,%3};"
        : "+f"(d[0]), "+f"(d[1]), "+f"(d[2]), "+f"(d[3])
        : "r"(a[0]), "r"(a[1]), "r"(a[2]), "r"(a[3]), "r"(b0), "r"(b1));
}

__device__ __forceinline__ void cp_async16(uint32_t smem, const void* g, bool pred) {
    int sz = pred ? 16 : 0;
    asm volatile("cp.async.cg.shared.global [%0], [%1], 16, %2;"
                 :: "r"(smem), "l"(g), "r"(sz) : "memory");
}
#define CP_COMMIT() asm volatile("cp.async.commit_group;" ::: "memory")
#define CP_WAIT1()  asm volatile("cp.async.wait_group 1;" ::: "memory")

template <bool RELU, typename CT>
__global__ __launch_bounds__(256, 2) void gemm_h_fused(GemmSideH sa, GemmSideH sb, int mblk_a) {
    extern __shared__ __align__(16) char dsmem[];
    const uint32_t sm0 = smem_u32(dsmem);

    const bool sideA = (int)blockIdx.x < mblk_a;
    const __half* A1 = sideA ? sa.A1 : sb.A1;
    const __half* W1 = sideA ? sa.W1 : sb.W1;
    const __half* A2 = sideA ? sa.A2 : sb.A2;
    const __half* W2 = sideA ? sa.W2 : sb.W2;
    const float* bias = sideA ? sa.bias : sb.bias;
    CT* C = (CT*)(sideA ? sa.C : sb.C);
    const int K1 = sideA ? sa.K1 : sb.K1;
    const int K2 = sideA ? sa.K2 : sb.K2;
    const int M  = sideA ? sa.M  : sb.M;
    const int mb = sideA ? blockIdx.x : blockIdx.x - mblk_a;

    const int tid = threadIdx.x;
    const int wid = tid >> 5;
    const int lane = tid & 31;
    const int warp_m = wid >> 2;
    const int warp_n = wid & 3;
    const int m0 = mb * 128;
    const int n0 = blockIdx.y * 128;

    const int row0 = tid >> 2;
    const int cc8 = (tid & 3) * 8;
    const uint32_t stoff = (uint32_t)(row0 * HROW_B + (tid & 3) * 16);

    float acc[4][4][4];
#pragma unroll
    for (int i = 0; i < 4; i++)
#pragma unroll
        for (int j = 0; j < 4; j++)
#pragma unroll
            for (int k = 0; k < 4; k++) acc[i][j][k] = 0.f;

    const int n1 = K1 / 32;
    const int n2 = K2 / 32;
    const int T = n1 + n2;

    auto issue_g = [&](int it, int slot) {
        const __half* A; const __half* W; int K, k0;
        if (it < n1) { A = A1; W = W1; K = K1; k0 = it * 32; }
        else         { A = A2; W = W2; K = K2; k0 = (it - n1) * 32; }
        const int cc = k0 + cc8;
        const uint32_t bA = sm0 + slot * HSTAGE;
        const uint32_t bB = bA + HSTAGE_A;
#pragma unroll
        for (int q = 0; q < 2; q++) {
            const int r = row0 + 64 * q;
            cp_async16(bA + stoff + (uint32_t)(64 * q * HROW_B),
                       A + (size_t)(m0 + r) * K + cc, m0 + r < M);
            cp_async16(bB + stoff + (uint32_t)(64 * q * HROW_B),
                       W + (size_t)(n0 + r) * K + cc, true);
        }
    };

    const int rowsel = (lane & 7) | (((lane >> 3) & 1) << 3);
    const int colsel = (lane >> 4) * 16;

    auto compute_s = [&](int st) {
        const uint32_t bA = sm0 + st * HSTAGE;
        const uint32_t bB = bA + HSTAGE_A;
        const uint32_t aBase = bA + (uint32_t)((warp_m * 64 + rowsel) * HROW_B + colsel);
        const uint32_t bBase = bB + (uint32_t)((warp_n * 32 + rowsel) * HROW_B + colsel);
#pragma unroll
        for (int ks = 0; ks < 2; ks++) {
            const uint32_t ko = ks * 32;
            uint32_t af[4][4], bf[8];
#pragma unroll
            for (int i = 0; i < 4; i++)
                ldsm_x4(af[i], aBase + i * (16 * HROW_B) + ko);
            ldsm_x4(bf + 0, bBase + ko);
            ldsm_x4(bf + 4, bBase + 16 * HROW_B + ko);
#pragma unroll
            for (int i = 0; i < 4; i++)
#pragma unroll
                for (int j = 0; j < 4; j++) {
                    const int bi = (j >> 1) * 4 + (j & 1);
                    mma_f16(acc[i][j], af[i], bf[bi], bf[bi + 2]);
                }
        }
    };

    issue_g(0, 0);
    CP_COMMIT();
    if (T > 1) issue_g(1, 1);
    CP_COMMIT();
    CP_WAIT1();
    __syncthreads();

    int slot = 0;
#pragma unroll 1
    for (int it = 0; it < T; it++) {
        compute_s(slot);
        if (it + 2 < T) issue_g(it + 2, (it + 2) % NSTAGE);
        CP_COMMIT();
        CP_WAIT1();
        __syncthreads();
        slot = (slot + 1 == NSTAGE) ? 0 : slot + 1;
    }

    const int g = lane >> 2;
    const int t = lane & 3;
#pragma unroll
    for (int j = 0; j < 4; j++) {
        const int nb = n0 + warp_n * 32 + j * 8 + t * 2;
        const float bx = bias[nb], by = bias[nb + 1];
#pragma unroll
        for (int i = 0; i < 4; i++) {
            const int rlo = m0 + warp_m * 64 + i * 16 + g;
            if (rlo < M) {
                float vx = acc[i][j][0] + bx, vy = acc[i][j][1] + by;
                if (RELU) { vx = fmaxf(vx, 0.f); vy = fmaxf(vy, 0.f); }
                if constexpr (sizeof(CT) == 2) {
                    __half2 hv = __float22half2_rn(make_float2(vx, vy));
                    *(__half2*)((__half*)C + (size_t)rlo * HH + nb) = hv;
                } else {
                    *(float2*)((float*)C + (size_t)rlo * HH + nb) = make_float2(vx, vy);
                }
            }
            const int rhi = rlo + 8;
            if (rhi < M) {
                float vx = acc[i][j][2] + bx, vy = acc[i][j][3] + by;
                if (RELU) { vx = fmaxf(vx, 0.f); vy = fmaxf(vy, 0.f); }
                if constexpr (sizeof(CT) == 2) {
                    __half2 hv = __float22half2_rn(make_float2(vx, vy));
                    *(__half2*)((__half*)C + (size_t)rhi * HH + nb) = hv;
                } else {
                    *(float2*)((float*)C + (size_t)rhi * HH + nb) = make_float2(vx, vy);
                }
            }
        }
    }
}

// ---------------- host ----------------
extern "C" void kernel_launch(void* const* d_in, const int* in_sizes, int n_in,
                              void* d_out, int out_size) {
    const float* x_user = (const float*)d_in[0];
    const float* x_item = (const float*)d_in[1];
    const int* ui_src = (const int*)d_in[2];
    const int* ui_dst = (const int*)d_in[3];
    const int* iu_src = (const int*)d_in[4];
    const int* iu_dst = (const int*)d_in[5];
    const float* W1l_ui = (const float*)d_in[6];
    const float* b1_ui  = (const float*)d_in[7];
    const float* W1r_ui = (const float*)d_in[8];
    const float* W1l_iu = (const float*)d_in[9];
    const float* b1_iu  = (const float*)d_in[10];
    const float* W1r_iu = (const float*)d_in[11];
    const float* W2l_ui = (const float*)d_in[12];
    const float* b2_ui  = (const float*)d_in[13];
    const float* W2r_ui = (const float*)d_in[14];
    const float* W2l_iu = (const float*)d_in[15];
    const float* b2_iu  = (const float*)d_in[16];
    const float* W2r_iu = (const float*)d_in[17];

    __half *xu_h, *xi_h, *agg_item_h, *agg_user_h, *h_item_h, *h_user_h,
           *aggH_item_h, *aggH_user_h, *w_h;
    cudaGetSymbolAddress((void**)&xu_h, g_xu_h);
    cudaGetSymbolAddress((void**)&xi_h, g_xi_h);
    cudaGetSymbolAddress((void**)&agg_item_h, g_agg_item_h);
    cudaGetSymbolAddress((void**)&agg_user_h, g_agg_user_h);
    cudaGetSymbolAddress((void**)&h_item_h, g_h_item_h);
    cudaGetSymbolAddress((void**)&h_user_h, g_h_user_h);
    cudaGetSymbolAddress((void**)&aggH_item_h, g_aggH_item_h);
    cudaGetSymbolAddress((void**)&aggH_user_h, g_aggH_user_h);
    cudaGetSymbolAddress((void**)&w_h, g_w_h);

    cudaFuncSetAttribute(gemm_h_fused<true, __half>,
                         cudaFuncAttributeMaxDynamicSharedMemorySize, HGEMM_SMEM);
    cudaFuncSetAttribute(gemm_h_fused<false, float>,
                         cudaFuncAttributeMaxDynamicSharedMemorySize, HGEMM_SMEM);

    // fp32 -> fp16 pre-convert (features + weights) + scratch zeroing
    {
        CvtArgs a;
        a.seg[0] = { x_user, xu_h, (N_USERC * DU) / 4 };
        a.seg[1] = { x_item, xi_h, (N_ITEMC * DI) / 4 };
        a.seg[2] = { W1l_ui, w_h + O_W1L_UI, (HH * DU) / 4 };
        a.seg[3] = { W1r_ui, w_h + O_W1R_UI, (HH * DI) / 4 };
        a.seg[4] = { W1l_iu, w_h + O_W1L_IU, (HH * DI) / 4 };
        a.seg[5] = { W1r_iu, w_h + O_W1R_IU, (HH * DU) / 4 };
        a.seg[6] = { W2l_ui, w_h + O_W2L_UI, (HH * HH) / 4 };
        a.seg[7] = { W2r_ui, w_h + O_W2R_UI, (HH * HH) / 4 };
        a.seg[8] = { W2l_iu, w_h + O_W2L_IU, (HH * HH) / 4 };
        a.seg[9] = { W2r_iu, w_h + O_W2R_IU, (HH * HH) / 4 };
        cvt_kernel<<<1024, 256>>>(a);
    }

    // CSR build (4 edges per thread; cur seeded by scan)
    count_kernel<<<(NE / 4 + 255) / 256, 256>>>(ui_dst, iu_dst);
    scan_lookback_kernel<<<dim3(98, 2), 256>>>();
    fill_kernel<<<(NE / 4 + 255) / 256, 256>>>(ui_src, ui_dst, iu_src, iu_dst);

    // layer 1 aggregation (fp16 features, fp32 accumulate)
    agg_l1_kernel<<<AGG_BLK_ITEM + AGG_BLK_USER, 256>>>();

    // layer 1 fused GEMMs (fp16 in, fp16 out + relu)
    {
        GemmSideH si = { agg_item_h, w_h + O_W1L_UI, xi_h, w_h + O_W1R_UI,
                         b1_ui, h_item_h, DU, DI, N_ITEMC };
        GemmSideH su = { agg_user_h, w_h + O_W1L_IU, xu_h, w_h + O_W1R_IU,
                         b1_iu, h_user_h, DI, DU, N_USERC };
        gemm_h_fused<true, __half><<<dim3(MBLK_ITEM + MBLK_USER, 2), 256, HGEMM_SMEM>>>(
            si, su, MBLK_ITEM);
    }

    // layer 2 aggregation
    agg_l2_kernel<<<AGG_BLK_ITEM + AGG_BLK_USER, 256>>>();

    // layer 2 fused GEMMs (fp16 in, fp32 out)
    float* out_user = (float*)d_out;
    float* out_item = out_user + (size_t)N_USERC * HH;
    {
        GemmSideH si = { aggH_item_h, w_h + O_W2L_UI, h_item_h, w_h + O_W2R_UI,
                         b2_ui, out_item, HH, HH, N_ITEMC };
        GemmSideH su = { aggH_user_h, w_h + O_W2L_IU, h_user_h, w_h + O_W2R_IU,
                         b2_iu, out_user, HH, HH, N_USERC };
        gemm_h_fused<false, float><<<dim3(MBLK_ITEM + MBLK_USER, 2), 256, HGEMM_SMEM>>>(
            si, su, MBLK_ITEM);
    }
}

// round 13
// speedup vs baseline: 1.5188x; 1.0786x over previous
#include <cuda_runtime.h>
#include <cuda_fp16.h>
#include <cstdint>

#define N_USERC 100000
#define N_ITEMC 50000
#define NE      1600000
#define DU      128
#define DI      64
#define HH      256

#define AGG_BLK_ITEM ((N_ITEMC + 7) / 8)     // 6250
#define AGG_BLK_USER ((N_USERC + 7) / 8)     // 12500
#define MBLK_ITEM ((N_ITEMC + 127) / 128)    // 391
#define MBLK_USER ((N_USERC + 127) / 128)    // 782

// ---------------- device scratch ----------------
__device__ __align__(16) int g_cnt_item[N_ITEMC];
__device__ __align__(16) int g_cnt_user[N_USERC];
__device__ __align__(16) int g_cur_item[N_ITEMC];   // seeded with rs (write cursors)
__device__ __align__(16) int g_cur_user[N_USERC];
__device__ __align__(16) int g_rs_item[N_ITEMC + 1];
__device__ __align__(16) int g_rs_user[N_USERC + 1];
__device__ __align__(16) int g_col_ui[NE];
__device__ __align__(16) int g_col_iu[NE];

__device__ unsigned int g_tkt[2];
__device__ __align__(16) unsigned long long g_desc[2][160];

__device__ __align__(128) __half g_xu_h[(size_t)N_USERC * DU];
__device__ __align__(128) __half g_xi_h[(size_t)N_ITEMC * DI];
__device__ __align__(128) __half g_agg_item_h[(size_t)N_ITEMC * DU];
__device__ __align__(128) __half g_agg_user_h[(size_t)N_USERC * DI];
__device__ __align__(128) __half g_h_item_h[(size_t)N_ITEMC * HH];
__device__ __align__(128) __half g_h_user_h[(size_t)N_USERC * HH];
__device__ __align__(128) __half g_aggH_item_h[(size_t)N_ITEMC * HH];
__device__ __align__(128) __half g_aggH_user_h[(size_t)N_USERC * HH];
__device__ __align__(128) __half g_w_h[360448];

// weight offsets in g_w_h
#define O_W1L_UI 0
#define O_W1R_UI 32768
#define O_W1L_IU 49152
#define O_W1R_IU 65536
#define O_W2L_UI 98304
#define O_W2R_UI 163840
#define O_W2L_IU 229376
#define O_W2R_IU 294912

// ---------------- fp32 -> fp16 convert (pure; zeroing via memsets) ----------------
struct CvtSeg { const float* s; __half* d; int n4; };
struct CvtArgs { CvtSeg seg[10]; };

__global__ void cvt_kernel(CvtArgs args) {
    const int gid = blockIdx.x * blockDim.x + threadIdx.x;
    const int stride = gridDim.x * blockDim.x;
#pragma unroll 1
    for (int k = 0; k < 10; k++) {
        CvtSeg g = args.seg[k];
        for (int i = gid; i < g.n4; i += stride) {
            float4 v = __ldg((const float4*)g.s + i);
            __half2 h0 = __float22half2_rn(make_float2(v.x, v.y));
            __half2 h1 = __float22half2_rn(make_float2(v.z, v.w));
            uint2 o;
            o.x = *(uint32_t*)&h0;
            o.y = *(uint32_t*)&h1;
            ((uint2*)g.d)[i] = o;
        }
    }
}

// ---------------- CSR build (4 edges / thread for MLP) ----------------
__global__ void count_kernel(const int* __restrict__ ui_dst, const int* __restrict__ iu_dst) {
    int i = blockIdx.x * blockDim.x + threadIdx.x;
    if (i >= NE / 4) return;
    int4 a = __ldg((const int4*)ui_dst + i);
    int4 b = __ldg((const int4*)iu_dst + i);
    atomicAdd(&g_cnt_item[a.x], 1); atomicAdd(&g_cnt_item[a.y], 1);
    atomicAdd(&g_cnt_item[a.z], 1); atomicAdd(&g_cnt_item[a.w], 1);
    atomicAdd(&g_cnt_user[b.x], 1); atomicAdd(&g_cnt_user[b.y], 1);
    atomicAdd(&g_cnt_user[b.z], 1); atomicAdd(&g_cnt_user[b.w], 1);
}

// ---------------- decoupled-lookback scan; seeds cur with rs ----------------
__global__ void scan_lookback_kernel() {
    const int y = blockIdx.y;
    const int* __restrict__ cnt = y == 0 ? g_cnt_item : g_cnt_user;
    int* __restrict__ rs  = y == 0 ? g_rs_item  : g_rs_user;
    int* __restrict__ cur = y == 0 ? g_cur_item : g_cur_user;
    const int n = y == 0 ? N_ITEMC : N_USERC;
    const int nblk = (n + 1023) / 1024;
    if (blockIdx.x >= nblk) return;

    __shared__ int s_vb;
    __shared__ int s_wsum[8];
    __shared__ int s_run;
    const int tid = threadIdx.x, lane = tid & 31, wid = tid >> 5;

    if (tid == 0) s_vb = atomicAdd(&g_tkt[y], 1u);
    __syncthreads();
    const int vb = s_vb;
    const int base = vb * 1024 + tid * 4;

    int v0 = 0, v1 = 0, v2 = 0, v3 = 0;
    if (base + 3 < n) {
        v0 = cnt[base]; v1 = cnt[base + 1]; v2 = cnt[base + 2]; v3 = cnt[base + 3];
    } else {
        if (base     < n) v0 = cnt[base];
        if (base + 1 < n) v1 = cnt[base + 1];
        if (base + 2 < n) v2 = cnt[base + 2];
        if (base + 3 < n) v3 = cnt[base + 3];
    }
    const int tot = v0 + v1 + v2 + v3;
    int inc = tot;
#pragma unroll
    for (int o = 1; o < 32; o <<= 1) {
        int u = __shfl_up_sync(0xffffffffu, inc, o);
        if (lane >= o) inc += u;
    }
    if (lane == 31) s_wsum[wid] = inc;
    __syncthreads();
    if (wid == 0) {
        int w = (lane < 8) ? s_wsum[lane] : 0;
#pragma unroll
        for (int o = 1; o < 8; o <<= 1) {
            int u = __shfl_up_sync(0xffffffffu, w, o);
            if (lane >= o) w += u;
        }
        if (lane < 8) s_wsum[lane] = w;
    }
    __syncthreads();
    const int agg = s_wsum[7];
    const int thr_exc = (wid ? s_wsum[wid - 1] : 0) + inc - tot;

    if (tid == 0) {
        if (vb == 0) {
            atomicExch(&g_desc[y][0], (2ull << 32) | (unsigned)agg);
            s_run = 0;
        } else {
            atomicExch(&g_desc[y][vb], (1ull << 32) | (unsigned)agg);
            int run = 0, p = vb - 1;
            while (true) {
                unsigned long long d;
                do { d = atomicAdd(&g_desc[y][p], 0ull); } while ((d >> 32) == 0ull);
                run += (int)(d & 0xffffffffull);
                if ((d >> 32) == 2ull) break;
                p--;
            }
            atomicExch(&g_desc[y][vb], (2ull << 32) | (unsigned)(run + agg));
            s_run = run;
        }
    }
    __syncthreads();
    const int run = s_run;
    const int e0 = run + thr_exc;
    if (base     < n) { int v = e0;                rs[base]     = v; cur[base]     = v; }
    if (base + 1 < n) { int v = e0 + v0;           rs[base + 1] = v; cur[base + 1] = v; }
    if (base + 2 < n) { int v = e0 + v0 + v1;      rs[base + 2] = v; cur[base + 2] = v; }
    if (base + 3 < n) { int v = e0 + v0 + v1 + v2; rs[base + 3] = v; cur[base + 3] = v; }
    if (vb == nblk - 1 && tid == 0) rs[n] = run + agg;
}

// fill: single atomic per edge (cursor pre-seeded with row start; no rs load)
__global__ void fill_kernel(const int* __restrict__ ui_src, const int* __restrict__ ui_dst,
                            const int* __restrict__ iu_src, const int* __restrict__ iu_dst) {
    int i = blockIdx.x * blockDim.x + threadIdx.x;
    if (i >= NE / 4) return;
    int4 us = __ldg((const int4*)ui_src + i);
    int4 ud = __ldg((const int4*)ui_dst + i);
    int4 is = __ldg((const int4*)iu_src + i);
    int4 id = __ldg((const int4*)iu_dst + i);
    {
        int p0 = atomicAdd(&g_cur_item[ud.x], 1);
        int p1 = atomicAdd(&g_cur_item[ud.y], 1);
        int p2 = atomicAdd(&g_cur_item[ud.z], 1);
        int p3 = atomicAdd(&g_cur_item[ud.w], 1);
        g_col_ui[p0] = us.x;
        g_col_ui[p1] = us.y;
        g_col_ui[p2] = us.z;
        g_col_ui[p3] = us.w;
    }
    {
        int p0 = atomicAdd(&g_cur_user[id.x], 1);
        int p1 = atomicAdd(&g_cur_user[id.y], 1);
        int p2 = atomicAdd(&g_cur_user[id.z], 1);
        int p3 = atomicAdd(&g_cur_user[id.w], 1);
        g_col_iu[p0] = is.x;
        g_col_iu[p1] = is.y;
        g_col_iu[p2] = is.z;
        g_col_iu[p3] = is.w;
    }
}

// ---------------- fp16 gather-based segment mean ----------------
template <int HV>
__device__ __forceinline__ void ld_row(const __half* p, int lane, uint32_t* raw) {
    if constexpr (HV == 4) {
        uint4 t = __ldg((const uint4*)p + lane);
        raw[0] = t.x; raw[1] = t.y; raw[2] = t.z; raw[3] = t.w;
    } else if constexpr (HV == 2) {
        uint2 t = __ldg((const uint2*)p + lane);
        raw[0] = t.x; raw[1] = t.y;
    } else {
        raw[0] = __ldg((const uint32_t*)p + lane);
    }
}

template <int HV>
__device__ __forceinline__ void agg_body_h(const __half* __restrict__ X,
                                           const int* __restrict__ rs,
                                           const int* __restrict__ col,
                                           __half* __restrict__ out, int w, int lane) {
    const int F = HV * 64;
    int s = rs[w], e = rs[w + 1];
    float2 acc[4][HV];
#pragma unroll
    for (int u = 0; u < 4; u++)
#pragma unroll
        for (int v = 0; v < HV; v++) acc[u][v] = make_float2(0.f, 0.f);

    int j = s;
    for (; j + 3 < e; j += 4) {
        uint32_t raw[4][HV];
#pragma unroll
        for (int u = 0; u < 4; u++)
            ld_row<HV>(X + (size_t)col[j + u] * F, lane, raw[u]);
#pragma unroll
        for (int u = 0; u < 4; u++)
#pragma unroll
            for (int v = 0; v < HV; v++) {
                float2 f = __half22float2(*(__half2*)&raw[u][v]);
                acc[u][v].x += f.x; acc[u][v].y += f.y;
            }
    }
    for (; j < e; j++) {
        uint32_t raw[HV];
        ld_row<HV>(X + (size_t)col[j] * F, lane, raw);
#pragma unroll
        for (int v = 0; v < HV; v++) {
            float2 f = __half22float2(*(__half2*)&raw[v]);
            acc[0][v].x += f.x; acc[0][v].y += f.y;
        }
    }
    float inv = (e > s) ? 1.0f / (float)(e - s) : 0.0f;
    uint32_t o[HV];
#pragma unroll
    for (int v = 0; v < HV; v++) {
        float2 m;
        m.x = (acc[0][v].x + acc[1][v].x + acc[2][v].x + acc[3][v].x) * inv;
        m.y = (acc[0][v].y + acc[1][v].y + acc[2][v].y + acc[3][v].y) * inv;
        __half2 h = __float22half2_rn(m);
        o[v] = *(uint32_t*)&h;
    }
    __half* orow = out + (size_t)w * F;
    if constexpr (HV == 4) ((uint4*)orow)[lane] = make_uint4(o[0], o[1], o[2], o[3]);
    else if constexpr (HV == 2) ((uint2*)orow)[lane] = make_uint2(o[0], o[1]);
    else ((uint32_t*)orow)[lane] = o[0];
}

// generic single-side agg launch (one warp per destination row)
template <int HV>
__global__ __launch_bounds__(256) void agg_kernel(const __half* __restrict__ X,
                                                  const int* __restrict__ rs,
                                                  const int* __restrict__ col,
                                                  __half* __restrict__ out, int ndst) {
    int w = blockIdx.x * 8 + (threadIdx.x >> 5);
    int lane = threadIdx.x & 31;
    if (w < ndst) agg_body_h<HV>(X, rs, col, out, w, lane);
}

// ================= fp16 mma.sync dual-A GEMM, cp.async 3-stage =================
#define HROW_B    80
#define HSTAGE_A  (128 * HROW_B)           // 10240
#define HSTAGE    (2 * HSTAGE_A)           // 20480
#define NSTAGE    3
#define HGEMM_SMEM (NSTAGE * HSTAGE)       // 61440

struct GemmSideH {
    const __half *A1, *W1, *A2, *W2;
    const float* bias;
    void* C;
    int K1, K2, M;
};

__device__ __forceinline__ uint32_t smem_u32(const void* p) {
    uint32_t a;
    asm("{ .reg .u64 t; cvta.to.shared.u64 t, %1; cvt.u32.u64 %0, t; }" : "=r"(a) : "l"(p));
    return a;
}

__device__ __forceinline__ void ldsm_x4(uint32_t* r, uint32_t addr) {
    asm volatile("ldmatrix.sync.aligned.m8n8.x4.shared.b16 {%0,%1,%2,%3}, [%4];"
                 : "=r"(r[0]), "=r"(r[1]), "=r"(r[2]), "=r"(r[3]) : "r"(addr));
}

__device__ __forceinline__ void mma_f16(float* d, const uint32_t* a, uint32_t b0, uint32_t b1) {
    asm volatile(
        "mma.sync.aligned.m16n8k16.row.col.f32.f16.f16.f32 "
        "{%0,%1,%2,%3}, {%4,%5,%6,%7}, {%8,%9}, {%0,%1,%2,%3};"
        : "+f"(d[0]), "+f"(d[1]), "+f"(d[2]), "+f"(d[3])
        : "r"(a[0]), "r"(a[1]), "r"(a[2]), "r"(a[3]), "r"(b0), "r"(b1));
}

__device__ __forceinline__ void cp_async16(uint32_t smem, const void* g, bool pred) {
    int sz = pred ? 16 : 0;
    asm volatile("cp.async.cg.shared.global [%0], [%1], 16, %2;"
                 :: "r"(smem), "l"(g), "r"(sz) : "memory");
}
#define CP_COMMIT() asm volatile("cp.async.commit_group;" ::: "memory")
#define CP_WAIT1()  asm volatile("cp.async.wait_group 1;" ::: "memory")

template <bool RELU, typename CT>
__global__ __launch_bounds__(256, 2) void gemm_h_fused(GemmSideH sa, GemmSideH sb, int mblk_a) {
    extern __shared__ __align__(16) char dsmem[];
    const uint32_t sm0 = smem_u32(dsmem);

    const bool sideA = (int)blockIdx.x < mblk_a;
    const __half* A1 = sideA ? sa.A1 : sb.A1;
    const __half* W1 = sideA ? sa.W1 : sb.W1;
    const __half* A2 = sideA ? sa.A2 : sb.A2;
    const __half* W2 = sideA ? sa.W2 : sb.W2;
    const float* bias = sideA ? sa.bias : sb.bias;
    CT* C = (CT*)(sideA ? sa.C : sb.C);
    const int K1 = sideA ? sa.K1 : sb.K1;
    const int K2 = sideA ? sa.K2 : sb.K2;
    const int M  = sideA ? sa.M  : sb.M;
    const int mb = sideA ? blockIdx.x : blockIdx.x - mblk_a;

    const int tid = threadIdx.x;
    const int wid = tid >> 5;
    const int lane = tid & 31;
    const int warp_m = wid >> 2;
    const int warp_n = wid & 3;
    const int m0 = mb * 128;
    const int n0 = blockIdx.y * 128;

    const int row0 = tid >> 2;
    const int cc8 = (tid & 3) * 8;
    const uint32_t stoff = (uint32_t)(row0 * HROW_B + (tid & 3) * 16);

    float acc[4][4][4];
#pragma unroll
    for (int i = 0; i < 4; i++)
#pragma unroll
        for (int j = 0; j < 4; j++)
#pragma unroll
            for (int k = 0; k < 4; k++) acc[i][j][k] = 0.f;

    const int n1 = K1 / 32;
    const int n2 = K2 / 32;
    const int T = n1 + n2;

    auto issue_g = [&](int it, int slot) {
        const __half* A; const __half* W; int K, k0;
        if (it < n1) { A = A1; W = W1; K = K1; k0 = it * 32; }
        else         { A = A2; W = W2; K = K2; k0 = (it - n1) * 32; }
        const int cc = k0 + cc8;
        const uint32_t bA = sm0 + slot * HSTAGE;
        const uint32_t bB = bA + HSTAGE_A;
#pragma unroll
        for (int q = 0; q < 2; q++) {
            const int r = row0 + 64 * q;
            cp_async16(bA + stoff + (uint32_t)(64 * q * HROW_B),
                       A + (size_t)(m0 + r) * K + cc, m0 + r < M);
            cp_async16(bB + stoff + (uint32_t)(64 * q * HROW_B),
                       W + (size_t)(n0 + r) * K + cc, true);
        }
    };

    const int rowsel = (lane & 7) | (((lane >> 3) & 1) << 3);
    const int colsel = (lane >> 4) * 16;

    auto compute_s = [&](int st) {
        const uint32_t bA = sm0 + st * HSTAGE;
        const uint32_t bB = bA + HSTAGE_A;
        const uint32_t aBase = bA + (uint32_t)((warp_m * 64 + rowsel) * HROW_B + colsel);
        const uint32_t bBase = bB + (uint32_t)((warp_n * 32 + rowsel) * HROW_B + colsel);
#pragma unroll
        for (int ks = 0; ks < 2; ks++) {
            const uint32_t ko = ks * 32;
            uint32_t af[4][4], bf[8];
#pragma unroll
            for (int i = 0; i < 4; i++)
                ldsm_x4(af[i], aBase + i * (16 * HROW_B) + ko);
            ldsm_x4(bf + 0, bBase + ko);
            ldsm_x4(bf + 4, bBase + 16 * HROW_B + ko);
#pragma unroll
            for (int i = 0; i < 4; i++)
#pragma unroll
                for (int j = 0; j < 4; j++) {
                    const int bi = (j >> 1) * 4 + (j & 1);
                    mma_f16(acc[i][j], af[i], bf[bi], bf[bi + 2]);
                }
        }
    };

    issue_g(0, 0);
    CP_COMMIT();
    if (T > 1) issue_g(1, 1);
    CP_COMMIT();
    CP_WAIT1();
    __syncthreads();

    int slot = 0;
#pragma unroll 1
    for (int it = 0; it < T; it++) {
        compute_s(slot);
        if (it + 2 < T) issue_g(it + 2, (it + 2) % NSTAGE);
        CP_COMMIT();
        CP_WAIT1();
        __syncthreads();
        slot = (slot + 1 == NSTAGE) ? 0 : slot + 1;
    }

    const int g = lane >> 2;
    const int t = lane & 3;
#pragma unroll
    for (int j = 0; j < 4; j++) {
        const int nb = n0 + warp_n * 32 + j * 8 + t * 2;
        const float bx = bias[nb], by = bias[nb + 1];
#pragma unroll
        for (int i = 0; i < 4; i++) {
            const int rlo = m0 + warp_m * 64 + i * 16 + g;
            if (rlo < M) {
                float vx = acc[i][j][0] + bx, vy = acc[i][j][1] + by;
                if (RELU) { vx = fmaxf(vx, 0.f); vy = fmaxf(vy, 0.f); }
                if constexpr (sizeof(CT) == 2) {
                    __half2 hv = __float22half2_rn(make_float2(vx, vy));
                    *(__half2*)((__half*)C + (size_t)rlo * HH + nb) = hv;
                } else {
                    *(float2*)((float*)C + (size_t)rlo * HH + nb) = make_float2(vx, vy);
                }
            }
            const int rhi = rlo + 8;
            if (rhi < M) {
                float vx = acc[i][j][2] + bx, vy = acc[i][j][3] + by;
                if (RELU) { vx = fmaxf(vx, 0.f); vy = fmaxf(vy, 0.f); }
                if constexpr (sizeof(CT) == 2) {
                    __half2 hv = __float22half2_rn(make_float2(vx, vy));
                    *(__half2*)((__half*)C + (size_t)rhi * HH + nb) = hv;
                } else {
                    *(float2*)((float*)C + (size_t)rhi * HH + nb) = make_float2(vx, vy);
                }
            }
        }
    }
}

// ---------------- host ----------------
extern "C" void kernel_launch(void* const* d_in, const int* in_sizes, int n_in,
                              void* d_out, int out_size) {
    const float* x_user = (const float*)d_in[0];
    const float* x_item = (const float*)d_in[1];
    const int* ui_src = (const int*)d_in[2];
    const int* ui_dst = (const int*)d_in[3];
    const int* iu_src = (const int*)d_in[4];
    const int* iu_dst = (const int*)d_in[5];
    const float* W1l_ui = (const float*)d_in[6];
    const float* b1_ui  = (const float*)d_in[7];
    const float* W1r_ui = (const float*)d_in[8];
    const float* W1l_iu = (const float*)d_in[9];
    const float* b1_iu  = (const float*)d_in[10];
    const float* W1r_iu = (const float*)d_in[11];
    const float* W2l_ui = (const float*)d_in[12];
    const float* b2_ui  = (const float*)d_in[13];
    const float* W2r_ui = (const float*)d_in[14];
    const float* W2l_iu = (const float*)d_in[15];
    const float* b2_iu  = (const float*)d_in[16];
    const float* W2r_iu = (const float*)d_in[17];

    int *cnt_item, *cnt_user, *rs_item, *rs_user, *col_ui, *col_iu;
    unsigned int* tkt;
    unsigned long long* desc;
    __half *xu_h, *xi_h, *agg_item_h, *agg_user_h, *h_item_h, *h_user_h,
           *aggH_item_h, *aggH_user_h, *w_h;
    cudaGetSymbolAddress((void**)&cnt_item, g_cnt_item);
    cudaGetSymbolAddress((void**)&cnt_user, g_cnt_user);
    cudaGetSymbolAddress((void**)&rs_item, g_rs_item);
    cudaGetSymbolAddress((void**)&rs_user, g_rs_user);
    cudaGetSymbolAddress((void**)&col_ui, g_col_ui);
    cudaGetSymbolAddress((void**)&col_iu, g_col_iu);
    cudaGetSymbolAddress((void**)&tkt, g_tkt);
    cudaGetSymbolAddress((void**)&desc, g_desc);
    cudaGetSymbolAddress((void**)&xu_h, g_xu_h);
    cudaGetSymbolAddress((void**)&xi_h, g_xi_h);
    cudaGetSymbolAddress((void**)&agg_item_h, g_agg_item_h);
    cudaGetSymbolAddress((void**)&agg_user_h, g_agg_user_h);
    cudaGetSymbolAddress((void**)&h_item_h, g_h_item_h);
    cudaGetSymbolAddress((void**)&h_user_h, g_h_user_h);
    cudaGetSymbolAddress((void**)&aggH_item_h, g_aggH_item_h);
    cudaGetSymbolAddress((void**)&aggH_user_h, g_aggH_user_h);
    cudaGetSymbolAddress((void**)&w_h, g_w_h);

    cudaFuncSetAttribute(gemm_h_fused<true, __half>,
                         cudaFuncAttributeMaxDynamicSharedMemorySize, HGEMM_SMEM);
    cudaFuncSetAttribute(gemm_h_fused<false, float>,
                         cudaFuncAttributeMaxDynamicSharedMemorySize, HGEMM_SMEM);

    // streams/events created once (first call is the non-captured correctness run)
    static cudaStream_t s2 = [] {
        cudaStream_t s; cudaStreamCreateWithFlags(&s, cudaStreamNonBlocking); return s;
    }();
    static cudaEvent_t evFork = [] {
        cudaEvent_t e; cudaEventCreateWithFlags(&e, cudaEventDisableTiming); return e;
    }();
    static cudaEvent_t evCvt = [] {
        cudaEvent_t e; cudaEventCreateWithFlags(&e, cudaEventDisableTiming); return e;
    }();
    static cudaEvent_t evFill = [] {
        cudaEvent_t e; cudaEventCreateWithFlags(&e, cudaEventDisableTiming); return e;
    }();
    static cudaEvent_t evHitem = [] {
        cudaEvent_t e; cudaEventCreateWithFlags(&e, cudaEventDisableTiming); return e;
    }();
    static cudaEvent_t evHuser = [] {
        cudaEvent_t e; cudaEventCreateWithFlags(&e, cudaEventDisableTiming); return e;
    }();
    static cudaEvent_t evDone = [] {
        cudaEvent_t e; cudaEventCreateWithFlags(&e, cudaEventDisableTiming); return e;
    }();

    // ---- fork: cvt on s2 ----
    cudaEventRecord(evFork, 0);
    cudaStreamWaitEvent(s2, evFork, 0);
    {
        CvtArgs a;
        a.seg[0] = { x_user, xu_h, (N_USERC * DU) / 4 };
        a.seg[1] = { x_item, xi_h, (N_ITEMC * DI) / 4 };
        a.seg[2] = { W1l_ui, w_h + O_W1L_UI, (HH * DU) / 4 };
        a.seg[3] = { W1r_ui, w_h + O_W1R_UI, (HH * DI) / 4 };
        a.seg[4] = { W1l_iu, w_h + O_W1L_IU, (HH * DI) / 4 };
        a.seg[5] = { W1r_iu, w_h + O_W1R_IU, (HH * DU) / 4 };
        a.seg[6] = { W2l_ui, w_h + O_W2L_UI, (HH * HH) / 4 };
        a.seg[7] = { W2r_ui, w_h + O_W2R_UI, (HH * HH) / 4 };
        a.seg[8] = { W2l_iu, w_h + O_W2L_IU, (HH * HH) / 4 };
        a.seg[9] = { W2r_iu, w_h + O_W2R_IU, (HH * HH) / 4 };
        cvt_kernel<<<1024, 256, 0, s2>>>(a);
    }
    cudaEventRecord(evCvt, s2);

    // ---- CSR chain on stream 0 (concurrent with cvt) ----
    cudaMemsetAsync(cnt_item, 0, N_ITEMC * sizeof(int), 0);
    cudaMemsetAsync(cnt_user, 0, N_USERC * sizeof(int), 0);
    cudaMemsetAsync(tkt, 0, 2 * sizeof(unsigned int), 0);
    cudaMemsetAsync(desc, 0, 2 * 160 * sizeof(unsigned long long), 0);
    count_kernel<<<(NE / 4 + 255) / 256, 256>>>(ui_dst, iu_dst);
    scan_lookback_kernel<<<dim3(98, 2), 256>>>();
    fill_kernel<<<(NE / 4 + 255) / 256, 256>>>(ui_src, ui_dst, iu_src, iu_dst);
    cudaEventRecord(evFill, 0);

    // ---- item chain on stream 0 ----
    cudaStreamWaitEvent(0, evCvt, 0);
    agg_kernel<2><<<AGG_BLK_ITEM, 256>>>(xu_h, rs_item, col_ui, agg_item_h, N_ITEMC);
    {
        GemmSideH si = { agg_item_h, w_h + O_W1L_UI, xi_h, w_h + O_W1R_UI,
                         b1_ui, h_item_h, DU, DI, N_ITEMC };
        gemm_h_fused<true, __half><<<dim3(MBLK_ITEM, 2), 256, HGEMM_SMEM>>>(si, si, MBLK_ITEM);
    }
    cudaEventRecord(evHitem, 0);

    // ---- user chain on s2 ----
    cudaStreamWaitEvent(s2, evFill, 0);
    agg_kernel<1><<<AGG_BLK_USER, 256, 0, s2>>>(xi_h, rs_user, col_iu, agg_user_h, N_USERC);
    {
        GemmSideH su = { agg_user_h, w_h + O_W1L_IU, xu_h, w_h + O_W1R_IU,
                         b1_iu, h_user_h, DI, DU, N_USERC };
        gemm_h_fused<true, __half><<<dim3(MBLK_USER, 2), 256, HGEMM_SMEM, s2>>>(su, su, MBLK_USER);
    }
    cudaEventRecord(evHuser, s2);

    float* out_user = (float*)d_out;
    float* out_item = out_user + (size_t)N_USERC * HH;

    // ---- layer 2 item chain on 0 (needs h_user from s2) ----
    cudaStreamWaitEvent(0, evHuser, 0);
    agg_kernel<4><<<AGG_BLK_ITEM, 256>>>(h_user_h, rs_item, col_ui, aggH_item_h, N_ITEMC);
    {
        GemmSideH si = { aggH_item_h, w_h + O_W2L_UI, h_item_h, w_h + O_W2R_UI,
                         b2_ui, out_item, HH, HH, N_ITEMC };
        gemm_h_fused<false, float><<<dim3(MBLK_ITEM, 2), 256, HGEMM_SMEM>>>(si, si, MBLK_ITEM);
    }

    // ---- layer 2 user chain on s2 (needs h_item from 0) ----
    cudaStreamWaitEvent(s2, evHitem, 0);
    agg_kernel<4><<<AGG_BLK_USER, 256, 0, s2>>>(h_item_h, rs_user, col_iu, aggH_user_h, N_USERC);
    {
        GemmSideH su = { aggH_user_h, w_h + O_W2L_IU, h_user_h, w_h + O_W2R_IU,
                         b2_iu, out_user, HH, HH, N_USERC };
        gemm_h_fused<false, float><<<dim3(MBLK_USER, 2), 256, HGEMM_SMEM, s2>>>(su, su, MBLK_USER);
    }
    cudaEventRecord(evDone, s2);

    // ---- final join back to the capture stream ----
    cudaStreamWaitEvent(0, evDone, 0);
}

// round 14
// speedup vs baseline: 1.5729x; 1.0356x over previous
#include <cuda_runtime.h>
#include <cuda_fp16.h>
#include <cstdint>

#define N_USERC 100000
#define N_ITEMC 50000
#define NE      1600000
#define DU      128
#define DI      64
#define HH      256

#define AGG_BLK_ITEM ((N_ITEMC + 7) / 8)     // 6250
#define AGG_BLK_USER ((N_USERC + 7) / 8)     // 12500
#define MBLK_ITEM ((N_ITEMC + 127) / 128)    // 391
#define MBLK_USER ((N_USERC + 127) / 128)    // 782

// ---------------- device scratch ----------------
__device__ __align__(16) int g_cnt_item[N_ITEMC];
__device__ __align__(16) int g_cnt_user[N_USERC];
__device__ __align__(16) int g_cur_item[N_ITEMC];   // seeded with rs (write cursors)
__device__ __align__(16) int g_cur_user[N_USERC];
__device__ __align__(16) int g_rs_item[N_ITEMC + 1];
__device__ __align__(16) int g_rs_user[N_USERC + 1];
__device__ __align__(16) int g_col_ui[NE];
__device__ __align__(16) int g_col_iu[NE];

__device__ unsigned int g_tkt[2];
__device__ __align__(16) unsigned long long g_desc[2][160];

__device__ __align__(128) __half g_xu_h[(size_t)N_USERC * DU];
__device__ __align__(128) __half g_xi_h[(size_t)N_ITEMC * DI];
__device__ __align__(128) __half g_agg_item_h[(size_t)N_ITEMC * DU];
__device__ __align__(128) __half g_agg_user_h[(size_t)N_USERC * DI];
__device__ __align__(128) __half g_h_item_h[(size_t)N_ITEMC * HH];
__device__ __align__(128) __half g_h_user_h[(size_t)N_USERC * HH];
__device__ __align__(128) __half g_aggH_item_h[(size_t)N_ITEMC * HH];
__device__ __align__(128) __half g_aggH_user_h[(size_t)N_USERC * HH];
__device__ __align__(128) __half g_w_h[360448];

// weight offsets in g_w_h
#define O_W1L_UI 0
#define O_W1R_UI 32768
#define O_W1L_IU 49152
#define O_W1R_IU 65536
#define O_W2L_UI 98304
#define O_W2R_UI 163840
#define O_W2L_IU 229376
#define O_W2R_IU 294912

// ---------------- fp32 -> fp16 convert (pure; zeroing via memsets) ----------------
struct CvtSeg { const float* s; __half* d; int n4; };
struct CvtArgs { CvtSeg seg[10]; };

__global__ void cvt_kernel(CvtArgs args) {
    const int gid = blockIdx.x * blockDim.x + threadIdx.x;
    const int stride = gridDim.x * blockDim.x;
#pragma unroll 1
    for (int k = 0; k < 10; k++) {
        CvtSeg g = args.seg[k];
        for (int i = gid; i < g.n4; i += stride) {
            float4 v = __ldg((const float4*)g.s + i);
            __half2 h0 = __float22half2_rn(make_float2(v.x, v.y));
            __half2 h1 = __float22half2_rn(make_float2(v.z, v.w));
            uint2 o;
            o.x = *(uint32_t*)&h0;
            o.y = *(uint32_t*)&h1;
            ((uint2*)g.d)[i] = o;
        }
    }
}

// ---------------- CSR build (4 edges / thread for MLP) ----------------
__global__ void count_kernel(const int* __restrict__ ui_dst, const int* __restrict__ iu_dst) {
    int i = blockIdx.x * blockDim.x + threadIdx.x;
    if (i >= NE / 4) return;
    int4 a = __ldg((const int4*)ui_dst + i);
    int4 b = __ldg((const int4*)iu_dst + i);
    atomicAdd(&g_cnt_item[a.x], 1); atomicAdd(&g_cnt_item[a.y], 1);
    atomicAdd(&g_cnt_item[a.z], 1); atomicAdd(&g_cnt_item[a.w], 1);
    atomicAdd(&g_cnt_user[b.x], 1); atomicAdd(&g_cnt_user[b.y], 1);
    atomicAdd(&g_cnt_user[b.z], 1); atomicAdd(&g_cnt_user[b.w], 1);
}

// ---------------- decoupled-lookback scan; seeds cur with rs ----------------
__global__ void scan_lookback_kernel() {
    const int y = blockIdx.y;
    const int* __restrict__ cnt = y == 0 ? g_cnt_item : g_cnt_user;
    int* __restrict__ rs  = y == 0 ? g_rs_item  : g_rs_user;
    int* __restrict__ cur = y == 0 ? g_cur_item : g_cur_user;
    const int n = y == 0 ? N_ITEMC : N_USERC;
    const int nblk = (n + 1023) / 1024;
    if (blockIdx.x >= nblk) return;

    __shared__ int s_vb;
    __shared__ int s_wsum[8];
    __shared__ int s_run;
    const int tid = threadIdx.x, lane = tid & 31, wid = tid >> 5;

    if (tid == 0) s_vb = atomicAdd(&g_tkt[y], 1u);
    __syncthreads();
    const int vb = s_vb;
    const int base = vb * 1024 + tid * 4;

    int v0 = 0, v1 = 0, v2 = 0, v3 = 0;
    if (base + 3 < n) {
        v0 = cnt[base]; v1 = cnt[base + 1]; v2 = cnt[base + 2]; v3 = cnt[base + 3];
    } else {
        if (base     < n) v0 = cnt[base];
        if (base + 1 < n) v1 = cnt[base + 1];
        if (base + 2 < n) v2 = cnt[base + 2];
        if (base + 3 < n) v3 = cnt[base + 3];
    }
    const int tot = v0 + v1 + v2 + v3;
    int inc = tot;
#pragma unroll
    for (int o = 1; o < 32; o <<= 1) {
        int u = __shfl_up_sync(0xffffffffu, inc, o);
        if (lane >= o) inc += u;
    }
    if (lane == 31) s_wsum[wid] = inc;
    __syncthreads();
    if (wid == 0) {
        int w = (lane < 8) ? s_wsum[lane] : 0;
#pragma unroll
        for (int o = 1; o < 8; o <<= 1) {
            int u = __shfl_up_sync(0xffffffffu, w, o);
            if (lane >= o) w += u;
        }
        if (lane < 8) s_wsum[lane] = w;
    }
    __syncthreads();
    const int agg = s_wsum[7];
    const int thr_exc = (wid ? s_wsum[wid - 1] : 0) + inc - tot;

    if (tid == 0) {
        if (vb == 0) {
            atomicExch(&g_desc[y][0], (2ull << 32) | (unsigned)agg);
            s_run = 0;
        } else {
            atomicExch(&g_desc[y][vb], (1ull << 32) | (unsigned)agg);
            int run = 0, p = vb - 1;
            while (true) {
                unsigned long long d;
                do { d = atomicAdd(&g_desc[y][p], 0ull); } while ((d >> 32) == 0ull);
                run += (int)(d & 0xffffffffull);
                if ((d >> 32) == 2ull) break;
                p--;
            }
            atomicExch(&g_desc[y][vb], (2ull << 32) | (unsigned)(run + agg));
            s_run = run;
        }
    }
    __syncthreads();
    const int run = s_run;
    const int e0 = run + thr_exc;
    if (base     < n) { int v = e0;                rs[base]     = v; cur[base]     = v; }
    if (base + 1 < n) { int v = e0 + v0;           rs[base + 1] = v; cur[base + 1] = v; }
    if (base + 2 < n) { int v = e0 + v0 + v1;      rs[base + 2] = v; cur[base + 2] = v; }
    if (base + 3 < n) { int v = e0 + v0 + v1 + v2; rs[base + 3] = v; cur[base + 3] = v; }
    if (vb == nblk - 1 && tid == 0) rs[n] = run + agg;
}

// per-side fill: single atomic per edge (cursor pre-seeded with row start)
__global__ void fill_side_kernel(const int* __restrict__ src, const int* __restrict__ dst,
                                 int* __restrict__ cur, int* __restrict__ col) {
    int i = blockIdx.x * blockDim.x + threadIdx.x;
    if (i >= NE / 4) return;
    int4 s4 = __ldg((const int4*)src + i);
    int4 d4 = __ldg((const int4*)dst + i);
    int p0 = atomicAdd(&cur[d4.x], 1);
    int p1 = atomicAdd(&cur[d4.y], 1);
    int p2 = atomicAdd(&cur[d4.z], 1);
    int p3 = atomicAdd(&cur[d4.w], 1);
    col[p0] = s4.x;
    col[p1] = s4.y;
    col[p2] = s4.z;
    col[p3] = s4.w;
}

// ---------------- fp16 gather-based segment mean ----------------
template <int HV>
__device__ __forceinline__ void ld_row(const __half* p, int lane, uint32_t* raw) {
    if constexpr (HV == 4) {
        uint4 t = __ldg((const uint4*)p + lane);
        raw[0] = t.x; raw[1] = t.y; raw[2] = t.z; raw[3] = t.w;
    } else if constexpr (HV == 2) {
        uint2 t = __ldg((const uint2*)p + lane);
        raw[0] = t.x; raw[1] = t.y;
    } else {
        raw[0] = __ldg((const uint32_t*)p + lane);
    }
}

template <int HV>
__device__ __forceinline__ void agg_body_h(const __half* __restrict__ X,
                                           const int* __restrict__ rs,
                                           const int* __restrict__ col,
                                           __half* __restrict__ out, int w, int lane) {
    const int F = HV * 64;
    int s = rs[w], e = rs[w + 1];
    float2 acc[4][HV];
#pragma unroll
    for (int u = 0; u < 4; u++)
#pragma unroll
        for (int v = 0; v < HV; v++) acc[u][v] = make_float2(0.f, 0.f);

    int j = s;
    for (; j + 3 < e; j += 4) {
        uint32_t raw[4][HV];
#pragma unroll
        for (int u = 0; u < 4; u++)
            ld_row<HV>(X + (size_t)col[j + u] * F, lane, raw[u]);
#pragma unroll
        for (int u = 0; u < 4; u++)
#pragma unroll
            for (int v = 0; v < HV; v++) {
                float2 f = __half22float2(*(__half2*)&raw[u][v]);
                acc[u][v].x += f.x; acc[u][v].y += f.y;
            }
    }
    for (; j < e; j++) {
        uint32_t raw[HV];
        ld_row<HV>(X + (size_t)col[j] * F, lane, raw);
#pragma unroll
        for (int v = 0; v < HV; v++) {
            float2 f = __half22float2(*(__half2*)&raw[v]);
            acc[0][v].x += f.x; acc[0][v].y += f.y;
        }
    }
    float inv = (e > s) ? 1.0f / (float)(e - s) : 0.0f;
    uint32_t o[HV];
#pragma unroll
    for (int v = 0; v < HV; v++) {
        float2 m;
        m.x = (acc[0][v].x + acc[1][v].x + acc[2][v].x + acc[3][v].x) * inv;
        m.y = (acc[0][v].y + acc[1][v].y + acc[2][v].y + acc[3][v].y) * inv;
        __half2 h = __float22half2_rn(m);
        o[v] = *(uint32_t*)&h;
    }
    __half* orow = out + (size_t)w * F;
    if constexpr (HV == 4) ((uint4*)orow)[lane] = make_uint4(o[0], o[1], o[2], o[3]);
    else if constexpr (HV == 2) ((uint2*)orow)[lane] = make_uint2(o[0], o[1]);
    else ((uint32_t*)orow)[lane] = o[0];
}

template <int HV>
__global__ __launch_bounds__(256) void agg_kernel(const __half* __restrict__ X,
                                                  const int* __restrict__ rs,
                                                  const int* __restrict__ col,
                                                  __half* __restrict__ out, int ndst) {
    int w = blockIdx.x * 8 + (threadIdx.x >> 5);
    int lane = threadIdx.x & 31;
    if (w < ndst) agg_body_h<HV>(X, rs, col, out, w, lane);
}

// ================= fp16 mma.sync dual-A GEMM, cp.async 3-stage =================
#define HROW_B    80
#define HSTAGE_A  (128 * HROW_B)           // 10240
#define HSTAGE    (2 * HSTAGE_A)           // 20480
#define NSTAGE    3
#define HGEMM_SMEM (NSTAGE * HSTAGE)       // 61440

struct GemmSideH {
    const __half *A1, *W1, *A2, *W2;
    const float* bias;
    void* C;
    int K1, K2, M;
};

__device__ __forceinline__ uint32_t smem_u32(const void* p) {
    uint32_t a;
    asm("{ .reg .u64 t; cvta.to.shared.u64 t, %1; cvt.u32.u64 %0, t; }" : "=r"(a) : "l"(p));
    return a;
}

__device__ __forceinline__ void ldsm_x4(uint32_t* r, uint32_t addr) {
    asm volatile("ldmatrix.sync.aligned.m8n8.x4.shared.b16 {%0,%1,%2,%3}, [%4];"
                 : "=r"(r[0]), "=r"(r[1]), "=r"(r[2]), "=r"(r[3]) : "r"(addr));
}

__device__ __forceinline__ void mma_f16(float* d, const uint32_t* a, uint32_t b0, uint32_t b1) {
    asm volatile(
        "mma.sync.aligned.m16n8k16.row.col.f32.f16.f16.f32 "
        "{%0,%1,%2,%3}, {%4,%5,%6,%7}, {%8,%9}, {%0,%1,%2,%3};"
        : "+f"(d[0]), "+f"(d[1]), "+f"(d[2]), "+f"(d[3])
        : "r"(a[0]), "r"(a[1]), "r"(a[2]), "r"(a[3]), "r"(b0), "r"(b1));
}

__device__ __forceinline__ void cp_async16(uint32_t smem, const void* g, bool pred) {
    int sz = pred ? 16 : 0;
    asm volatile("cp.async.cg.shared.global [%0], [%1], 16, %2;"
                 :: "r"(smem), "l"(g), "r"(sz) : "memory");
}
#define CP_COMMIT() asm volatile("cp.async.commit_group;" ::: "memory")
#define CP_WAIT1()  asm volatile("cp.async.wait_group 1;" ::: "memory")

template <bool RELU, typename CT>
__global__ __launch_bounds__(256, 2) void gemm_h_fused(GemmSideH sa, GemmSideH sb, int mblk_a) {
    extern __shared__ __align__(16) char dsmem[];
    const uint32_t sm0 = smem_u32(dsmem);

    const bool sideA = (int)blockIdx.x < mblk_a;
    const __half* A1 = sideA ? sa.A1 : sb.A1;
    const __half* W1 = sideA ? sa.W1 : sb.W1;
    const __half* A2 = sideA ? sa.A2 : sb.A2;
    const __half* W2 = sideA ? sa.W2 : sb.W2;
    const float* bias = sideA ? sa.bias : sb.bias;
    CT* C = (CT*)(sideA ? sa.C : sb.C);
    const int K1 = sideA ? sa.K1 : sb.K1;
    const int K2 = sideA ? sa.K2 : sb.K2;
    const int M  = sideA ? sa.M  : sb.M;
    const int mb = sideA ? blockIdx.x : blockIdx.x - mblk_a;

    const int tid = threadIdx.x;
    const int wid = tid >> 5;
    const int lane = tid & 31;
    const int warp_m = wid >> 2;
    const int warp_n = wid & 3;
    const int m0 = mb * 128;
    const int n0 = blockIdx.y * 128;

    const int row0 = tid >> 2;
    const int cc8 = (tid & 3) * 8;
    const uint32_t stoff = (uint32_t)(row0 * HROW_B + (tid & 3) * 16);

    float acc[4][4][4];
#pragma unroll
    for (int i = 0; i < 4; i++)
#pragma unroll
        for (int j = 0; j < 4; j++)
#pragma unroll
            for (int k = 0; k < 4; k++) acc[i][j][k] = 0.f;

    const int n1 = K1 / 32;
    const int n2 = K2 / 32;
    const int T = n1 + n2;

    auto issue_g = [&](int it, int slot) {
        const __half* A; const __half* W; int K, k0;
        if (it < n1) { A = A1; W = W1; K = K1; k0 = it * 32; }
        else         { A = A2; W = W2; K = K2; k0 = (it - n1) * 32; }
        const int cc = k0 + cc8;
        const uint32_t bA = sm0 + slot * HSTAGE;
        const uint32_t bB = bA + HSTAGE_A;
#pragma unroll
        for (int q = 0; q < 2; q++) {
            const int r = row0 + 64 * q;
            cp_async16(bA + stoff + (uint32_t)(64 * q * HROW_B),
                       A + (size_t)(m0 + r) * K + cc, m0 + r < M);
            cp_async16(bB + stoff + (uint32_t)(64 * q * HROW_B),
                       W + (size_t)(n0 + r) * K + cc, true);
        }
    };

    const int rowsel = (lane & 7) | (((lane >> 3) & 1) << 3);
    const int colsel = (lane >> 4) * 16;

    auto compute_s = [&](int st) {
        const uint32_t bA = sm0 + st * HSTAGE;
        const uint32_t bB = bA + HSTAGE_A;
        const uint32_t aBase = bA + (uint32_t)((warp_m * 64 + rowsel) * HROW_B + colsel);
        const uint32_t bBase = bB + (uint32_t)((warp_n * 32 + rowsel) * HROW_B + colsel);
#pragma unroll
        for (int ks = 0; ks < 2; ks++) {
            const uint32_t ko = ks * 32;
            uint32_t af[4][4], bf[8];
#pragma unroll
            for (int i = 0; i < 4; i++)
                ldsm_x4(af[i], aBase + i * (16 * HROW_B) + ko);
            ldsm_x4(bf + 0, bBase + ko);
            ldsm_x4(bf + 4, bBase + 16 * HROW_B + ko);
#pragma unroll
            for (int i = 0; i < 4; i++)
#pragma unroll
                for (int j = 0; j < 4; j++) {
                    const int bi = (j >> 1) * 4 + (j & 1);
                    mma_f16(acc[i][j], af[i], bf[bi], bf[bi + 2]);
                }
        }
    };

    issue_g(0, 0);
    CP_COMMIT();
    if (T > 1) issue_g(1, 1);
    CP_COMMIT();
    CP_WAIT1();
    __syncthreads();

    int slot = 0;
#pragma unroll 1
    for (int it = 0; it < T; it++) {
        compute_s(slot);
        if (it + 2 < T) issue_g(it + 2, (it + 2) % NSTAGE);
        CP_COMMIT();
        CP_WAIT1();
        __syncthreads();
        slot = (slot + 1 == NSTAGE) ? 0 : slot + 1;
    }

    const int g = lane >> 2;
    const int t = lane & 3;
#pragma unroll
    for (int j = 0; j < 4; j++) {
        const int nb = n0 + warp_n * 32 + j * 8 + t * 2;
        const float bx = bias[nb], by = bias[nb + 1];
#pragma unroll
        for (int i = 0; i < 4; i++) {
            const int rlo = m0 + warp_m * 64 + i * 16 + g;
            if (rlo < M) {
                float vx = acc[i][j][0] + bx, vy = acc[i][j][1] + by;
                if (RELU) { vx = fmaxf(vx, 0.f); vy = fmaxf(vy, 0.f); }
                if constexpr (sizeof(CT) == 2) {
                    __half2 hv = __float22half2_rn(make_float2(vx, vy));
                    *(__half2*)((__half*)C + (size_t)rlo * HH + nb) = hv;
                } else {
                    *(float2*)((float*)C + (size_t)rlo * HH + nb) = make_float2(vx, vy);
                }
            }
            const int rhi = rlo + 8;
            if (rhi < M) {
                float vx = acc[i][j][2] + bx, vy = acc[i][j][3] + by;
                if (RELU) { vx = fmaxf(vx, 0.f); vy = fmaxf(vy, 0.f); }
                if constexpr (sizeof(CT) == 2) {
                    __half2 hv = __float22half2_rn(make_float2(vx, vy));
                    *(__half2*)((__half*)C + (size_t)rhi * HH + nb) = hv;
                } else {
                    *(float2*)((float*)C + (size_t)rhi * HH + nb) = make_float2(vx, vy);
                }
            }
        }
    }
}

// ---------------- host ----------------
extern "C" void kernel_launch(void* const* d_in, const int* in_sizes, int n_in,
                              void* d_out, int out_size) {
    const float* x_user = (const float*)d_in[0];
    const float* x_item = (const float*)d_in[1];
    const int* ui_src = (const int*)d_in[2];
    const int* ui_dst = (const int*)d_in[3];
    const int* iu_src = (const int*)d_in[4];
    const int* iu_dst = (const int*)d_in[5];
    const float* W1l_ui = (const float*)d_in[6];
    const float* b1_ui  = (const float*)d_in[7];
    const float* W1r_ui = (const float*)d_in[8];
    const float* W1l_iu = (const float*)d_in[9];
    const float* b1_iu  = (const float*)d_in[10];
    const float* W1r_iu = (const float*)d_in[11];
    const float* W2l_ui = (const float*)d_in[12];
    const float* b2_ui  = (const float*)d_in[13];
    const float* W2r_ui = (const float*)d_in[14];
    const float* W2l_iu = (const float*)d_in[15];
    const float* b2_iu  = (const float*)d_in[16];
    const float* W2r_iu = (const float*)d_in[17];

    int *cnt_item, *cnt_user, *cur_item, *cur_user, *rs_item, *rs_user, *col_ui, *col_iu;
    unsigned int* tkt;
    unsigned long long* desc;
    __half *xu_h, *xi_h, *agg_item_h, *agg_user_h, *h_item_h, *h_user_h,
           *aggH_item_h, *aggH_user_h, *w_h;
    cudaGetSymbolAddress((void**)&cnt_item, g_cnt_item);
    cudaGetSymbolAddress((void**)&cnt_user, g_cnt_user);
    cudaGetSymbolAddress((void**)&cur_item, g_cur_item);
    cudaGetSymbolAddress((void**)&cur_user, g_cur_user);
    cudaGetSymbolAddress((void**)&rs_item, g_rs_item);
    cudaGetSymbolAddress((void**)&rs_user, g_rs_user);
    cudaGetSymbolAddress((void**)&col_ui, g_col_ui);
    cudaGetSymbolAddress((void**)&col_iu, g_col_iu);
    cudaGetSymbolAddress((void**)&tkt, g_tkt);
    cudaGetSymbolAddress((void**)&desc, g_desc);
    cudaGetSymbolAddress((void**)&xu_h, g_xu_h);
    cudaGetSymbolAddress((void**)&xi_h, g_xi_h);
    cudaGetSymbolAddress((void**)&agg_item_h, g_agg_item_h);
    cudaGetSymbolAddress((void**)&agg_user_h, g_agg_user_h);
    cudaGetSymbolAddress((void**)&h_item_h, g_h_item_h);
    cudaGetSymbolAddress((void**)&h_user_h, g_h_user_h);
    cudaGetSymbolAddress((void**)&aggH_item_h, g_aggH_item_h);
    cudaGetSymbolAddress((void**)&aggH_user_h, g_aggH_user_h);
    cudaGetSymbolAddress((void**)&w_h, g_w_h);

    cudaFuncSetAttribute(gemm_h_fused<true, __half>,
                         cudaFuncAttributeMaxDynamicSharedMemorySize, HGEMM_SMEM);
    cudaFuncSetAttribute(gemm_h_fused<false, float>,
                         cudaFuncAttributeMaxDynamicSharedMemorySize, HGEMM_SMEM);

    static cudaStream_t s2 = [] {
        cudaStream_t s; cudaStreamCreateWithFlags(&s, cudaStreamNonBlocking); return s;
    }();
    auto mkev = [] { cudaEvent_t e; cudaEventCreateWithFlags(&e, cudaEventDisableTiming); return e; };
    static cudaEvent_t evFork = mkev();
    static cudaEvent_t evCvt  = mkev();
    static cudaEvent_t evScan = mkev();
    static cudaEvent_t evHuser = mkev();
    static cudaEvent_t evA2i  = mkev();
    static cudaEvent_t evDone = mkev();

    // ---- fork: cvt on s2 (overlaps CSR build) ----
    cudaEventRecord(evFork, 0);
    cudaStreamWaitEvent(s2, evFork, 0);
    {
        CvtArgs a;
        a.seg[0] = { x_user, xu_h, (N_USERC * DU) / 4 };
        a.seg[1] = { x_item, xi_h, (N_ITEMC * DI) / 4 };
        a.seg[2] = { W1l_ui, w_h + O_W1L_UI, (HH * DU) / 4 };
        a.seg[3] = { W1r_ui, w_h + O_W1R_UI, (HH * DI) / 4 };
        a.seg[4] = { W1l_iu, w_h + O_W1L_IU, (HH * DI) / 4 };
        a.seg[5] = { W1r_iu, w_h + O_W1R_IU, (HH * DU) / 4 };
        a.seg[6] = { W2l_ui, w_h + O_W2L_UI, (HH * HH) / 4 };
        a.seg[7] = { W2r_ui, w_h + O_W2R_UI, (HH * HH) / 4 };
        a.seg[8] = { W2l_iu, w_h + O_W2L_IU, (HH * HH) / 4 };
        a.seg[9] = { W2r_iu, w_h + O_W2R_IU, (HH * HH) / 4 };
        cvt_kernel<<<1024, 256, 0, s2>>>(a);
    }
    cudaEventRecord(evCvt, s2);

    // ---- CSR head on stream 0 ----
    cudaMemsetAsync(cnt_item, 0, N_ITEMC * sizeof(int), 0);
    cudaMemsetAsync(cnt_user, 0, N_USERC * sizeof(int), 0);
    cudaMemsetAsync(tkt, 0, 2 * sizeof(unsigned int), 0);
    cudaMemsetAsync(desc, 0, 2 * 160 * sizeof(unsigned long long), 0);
    count_kernel<<<(NE / 4 + 255) / 256, 256>>>(ui_dst, iu_dst);
    scan_lookback_kernel<<<dim3(98, 2), 256>>>();
    cudaEventRecord(evScan, 0);

    // ---- item chain on s0: fill_item -> aggL1_item -> gemm1_item ----
    fill_side_kernel<<<(NE / 4 + 255) / 256, 256>>>(ui_src, ui_dst, cur_item, col_ui);
    cudaStreamWaitEvent(0, evCvt, 0);
    agg_kernel<2><<<AGG_BLK_ITEM, 256>>>(xu_h, rs_item, col_ui, agg_item_h, N_ITEMC);
    {
        GemmSideH si = { agg_item_h, w_h + O_W1L_UI, xi_h, w_h + O_W1R_UI,
                         b1_ui, h_item_h, DU, DI, N_ITEMC };
        gemm_h_fused<true, __half><<<dim3(MBLK_ITEM, 2), 256, HGEMM_SMEM>>>(si, si, MBLK_ITEM);
    }

    // ---- user chain on s2: fill_user -> aggL1_user -> gemm1_user ----
    cudaStreamWaitEvent(s2, evScan, 0);
    fill_side_kernel<<<(NE / 4 + 255) / 256, 256, 0, s2>>>(iu_src, iu_dst, cur_user, col_iu);
    agg_kernel<1><<<AGG_BLK_USER, 256, 0, s2>>>(xi_h, rs_user, col_iu, agg_user_h, N_USERC);
    {
        GemmSideH su = { agg_user_h, w_h + O_W1L_IU, xu_h, w_h + O_W1R_IU,
                         b1_iu, h_user_h, DI, DU, N_USERC };
        gemm_h_fused<true, __half><<<dim3(MBLK_USER, 2), 256, HGEMM_SMEM, s2>>>(su, su, MBLK_USER);
    }
    cudaEventRecord(evHuser, s2);

    float* out_user = (float*)d_out;
    float* out_item = out_user + (size_t)N_USERC * HH;

    // ---- layer 2, staggered: aggL2_item first (s0), then gemm2_item (tensor)
    //      runs concurrently with aggL2_user (LTS) on s2 ----
    cudaStreamWaitEvent(0, evHuser, 0);
    agg_kernel<4><<<AGG_BLK_ITEM, 256>>>(h_user_h, rs_item, col_ui, aggH_item_h, N_ITEMC);
    cudaEventRecord(evA2i, 0);
    {
        GemmSideH si = { aggH_item_h, w_h + O_W2L_UI, h_item_h, w_h + O_W2R_UI,
                         b2_ui, out_item, HH, HH, N_ITEMC };
        gemm_h_fused<false, float><<<dim3(MBLK_ITEM, 2), 256, HGEMM_SMEM>>>(si, si, MBLK_ITEM);
    }

    cudaStreamWaitEvent(s2, evA2i, 0);
    agg_kernel<4><<<AGG_BLK_USER, 256, 0, s2>>>(h_item_h, rs_user, col_iu, aggH_user_h, N_USERC);
    {
        GemmSideH su = { aggH_user_h, w_h + O_W2L_IU, h_user_h, w_h + O_W2R_IU,
                         b2_iu, out_user, HH, HH, N_USERC };
        gemm_h_fused<false, float><<<dim3(MBLK_USER, 2), 256, HGEMM_SMEM, s2>>>(su, su, MBLK_USER);
    }
    cudaEventRecord(evDone, s2);

    // ---- final join back to the capture stream ----
    cudaStreamWaitEvent(0, evDone, 0);
}

// round 15
// speedup vs baseline: 1.5739x; 1.0006x over previous
#include <cuda_runtime.h>
#include <cuda_fp16.h>
#include <cstdint>

#define N_USERC 100000
#define N_ITEMC 50000
#define NE      1600000
#define DU      128
#define DI      64
#define HH      256

#define AGG_BLK_ITEM ((N_ITEMC + 7) / 8)     // 6250
#define AGG_BLK_USER ((N_USERC + 7) / 8)     // 12500
#define MBLK_ITEM ((N_ITEMC + 127) / 128)    // 391
#define MBLK_USER ((N_USERC + 127) / 128)    // 782

// ---------------- device scratch ----------------
__device__ __align__(16) int g_cnt_item[N_ITEMC];
__device__ __align__(16) int g_cnt_user[N_USERC];
__device__ __align__(16) int g_cur_item[N_ITEMC];   // seeded with rs (write cursors)
__device__ __align__(16) int g_cur_user[N_USERC];
__device__ __align__(16) int g_rs_item[N_ITEMC + 1];
__device__ __align__(16) int g_rs_user[N_USERC + 1];
__device__ __align__(16) int g_col_ui[NE];
__device__ __align__(16) int g_col_iu[NE];

__device__ unsigned int g_tkt[2];
__device__ __align__(16) unsigned long long g_desc[2][160];

__device__ __align__(128) __half g_xu_h[(size_t)N_USERC * DU];
__device__ __align__(128) __half g_xi_h[(size_t)N_ITEMC * DI];
__device__ __align__(128) __half g_agg_item_h[(size_t)N_ITEMC * DU];
__device__ __align__(128) __half g_agg_user_h[(size_t)N_USERC * DI];
__device__ __align__(128) __half g_h_item_h[(size_t)N_ITEMC * HH];
__device__ __align__(128) __half g_h_user_h[(size_t)N_USERC * HH];
__device__ __align__(128) __half g_aggH_item_h[(size_t)N_ITEMC * HH];
__device__ __align__(128) __half g_aggH_user_h[(size_t)N_USERC * HH];
__device__ __align__(128) __half g_w_h[360448];

// weight offsets in g_w_h
#define O_W1L_UI 0
#define O_W1R_UI 32768
#define O_W1L_IU 49152
#define O_W1R_IU 65536
#define O_W2L_UI 98304
#define O_W2R_UI 163840
#define O_W2L_IU 229376
#define O_W2R_IU 294912

// ---------------- fp32 -> fp16 convert (pure; zeroing via memsets) ----------------
struct CvtSeg { const float* s; __half* d; int n4; };
struct CvtArgs { CvtSeg seg[10]; };

__global__ void cvt_kernel(CvtArgs args) {
    const int gid = blockIdx.x * blockDim.x + threadIdx.x;
    const int stride = gridDim.x * blockDim.x;
#pragma unroll 1
    for (int k = 0; k < 10; k++) {
        CvtSeg g = args.seg[k];
        for (int i = gid; i < g.n4; i += stride) {
            float4 v = __ldg((const float4*)g.s + i);
            __half2 h0 = __float22half2_rn(make_float2(v.x, v.y));
            __half2 h1 = __float22half2_rn(make_float2(v.z, v.w));
            uint2 o;
            o.x = *(uint32_t*)&h0;
            o.y = *(uint32_t*)&h1;
            ((uint2*)g.d)[i] = o;
        }
    }
}

// ---------------- CSR build (4 edges / thread for MLP) ----------------
__global__ void count_kernel(const int* __restrict__ ui_dst, const int* __restrict__ iu_dst) {
    int i = blockIdx.x * blockDim.x + threadIdx.x;
    if (i >= NE / 4) return;
    int4 a = __ldg((const int4*)ui_dst + i);
    int4 b = __ldg((const int4*)iu_dst + i);
    atomicAdd(&g_cnt_item[a.x], 1); atomicAdd(&g_cnt_item[a.y], 1);
    atomicAdd(&g_cnt_item[a.z], 1); atomicAdd(&g_cnt_item[a.w], 1);
    atomicAdd(&g_cnt_user[b.x], 1); atomicAdd(&g_cnt_user[b.y], 1);
    atomicAdd(&g_cnt_user[b.z], 1); atomicAdd(&g_cnt_user[b.w], 1);
}

// ---------------- decoupled-lookback scan; seeds cur with rs ----------------
__global__ void scan_lookback_kernel() {
    const int y = blockIdx.y;
    const int* __restrict__ cnt = y == 0 ? g_cnt_item : g_cnt_user;
    int* __restrict__ rs  = y == 0 ? g_rs_item  : g_rs_user;
    int* __restrict__ cur = y == 0 ? g_cur_item : g_cur_user;
    const int n = y == 0 ? N_ITEMC : N_USERC;
    const int nblk = (n + 1023) / 1024;
    if (blockIdx.x >= nblk) return;

    __shared__ int s_vb;
    __shared__ int s_wsum[8];
    __shared__ int s_run;
    const int tid = threadIdx.x, lane = tid & 31, wid = tid >> 5;

    if (tid == 0) s_vb = atomicAdd(&g_tkt[y], 1u);
    __syncthreads();
    const int vb = s_vb;
    const int base = vb * 1024 + tid * 4;

    int v0 = 0, v1 = 0, v2 = 0, v3 = 0;
    if (base + 3 < n) {
        v0 = cnt[base]; v1 = cnt[base + 1]; v2 = cnt[base + 2]; v3 = cnt[base + 3];
    } else {
        if (base     < n) v0 = cnt[base];
        if (base + 1 < n) v1 = cnt[base + 1];
        if (base + 2 < n) v2 = cnt[base + 2];
        if (base + 3 < n) v3 = cnt[base + 3];
    }
    const int tot = v0 + v1 + v2 + v3;
    int inc = tot;
#pragma unroll
    for (int o = 1; o < 32; o <<= 1) {
        int u = __shfl_up_sync(0xffffffffu, inc, o);
        if (lane >= o) inc += u;
    }
    if (lane == 31) s_wsum[wid] = inc;
    __syncthreads();
    if (wid == 0) {
        int w = (lane < 8) ? s_wsum[lane] : 0;
#pragma unroll
        for (int o = 1; o < 8; o <<= 1) {
            int u = __shfl_up_sync(0xffffffffu, w, o);
            if (lane >= o) w += u;
        }
        if (lane < 8) s_wsum[lane] = w;
    }
    __syncthreads();
    const int agg = s_wsum[7];
    const int thr_exc = (wid ? s_wsum[wid - 1] : 0) + inc - tot;

    if (tid == 0) {
        if (vb == 0) {
            atomicExch(&g_desc[y][0], (2ull << 32) | (unsigned)agg);
            s_run = 0;
        } else {
            atomicExch(&g_desc[y][vb], (1ull << 32) | (unsigned)agg);
            int run = 0, p = vb - 1;
            while (true) {
                unsigned long long d;
                do { d = atomicAdd(&g_desc[y][p], 0ull); } while ((d >> 32) == 0ull);
                run += (int)(d & 0xffffffffull);
                if ((d >> 32) == 2ull) break;
                p--;
            }
            atomicExch(&g_desc[y][vb], (2ull << 32) | (unsigned)(run + agg));
            s_run = run;
        }
    }
    __syncthreads();
    const int run = s_run;
    const int e0 = run + thr_exc;
    if (base     < n) { int v = e0;                rs[base]     = v; cur[base]     = v; }
    if (base + 1 < n) { int v = e0 + v0;           rs[base + 1] = v; cur[base + 1] = v; }
    if (base + 2 < n) { int v = e0 + v0 + v1;      rs[base + 2] = v; cur[base + 2] = v; }
    if (base + 3 < n) { int v = e0 + v0 + v1 + v2; rs[base + 3] = v; cur[base + 3] = v; }
    if (vb == nblk - 1 && tid == 0) rs[n] = run + agg;
}

// per-side fill: single atomic per edge (cursor pre-seeded with row start)
__global__ void fill_side_kernel(const int* __restrict__ src, const int* __restrict__ dst,
                                 int* __restrict__ cur, int* __restrict__ col) {
    int i = blockIdx.x * blockDim.x + threadIdx.x;
    if (i >= NE / 4) return;
    int4 s4 = __ldg((const int4*)src + i);
    int4 d4 = __ldg((const int4*)dst + i);
    int p0 = atomicAdd(&cur[d4.x], 1);
    int p1 = atomicAdd(&cur[d4.y], 1);
    int p2 = atomicAdd(&cur[d4.z], 1);
    int p3 = atomicAdd(&cur[d4.w], 1);
    col[p0] = s4.x;
    col[p1] = s4.y;
    col[p2] = s4.z;
    col[p3] = s4.w;
}

// ---------------- fp16 gather-based segment mean ----------------
template <int HV>
__device__ __forceinline__ void ld_row(const __half* p, int lane, uint32_t* raw) {
    if constexpr (HV == 4) {
        uint4 t = __ldg((const uint4*)p + lane);
        raw[0] = t.x; raw[1] = t.y; raw[2] = t.z; raw[3] = t.w;
    } else if constexpr (HV == 2) {
        uint2 t = __ldg((const uint2*)p + lane);
        raw[0] = t.x; raw[1] = t.y;
    } else {
        raw[0] = __ldg((const uint32_t*)p + lane);
    }
}

template <int HV>
__device__ __forceinline__ void agg_body_h(const __half* __restrict__ X,
                                           const int* __restrict__ rs,
                                           const int* __restrict__ col,
                                           __half* __restrict__ out, int w, int lane) {
    const int F = HV * 64;
    int s = rs[w], e = rs[w + 1];
    float2 acc[4][HV];
#pragma unroll
    for (int u = 0; u < 4; u++)
#pragma unroll
        for (int v = 0; v < HV; v++) acc[u][v] = make_float2(0.f, 0.f);

    int j = s;
    for (; j + 3 < e; j += 4) {
        uint32_t raw[4][HV];
#pragma unroll
        for (int u = 0; u < 4; u++)
            ld_row<HV>(X + (size_t)col[j + u] * F, lane, raw[u]);
#pragma unroll
        for (int u = 0; u < 4; u++)
#pragma unroll
            for (int v = 0; v < HV; v++) {
                float2 f = __half22float2(*(__half2*)&raw[u][v]);
                acc[u][v].x += f.x; acc[u][v].y += f.y;
            }
    }
    for (; j < e; j++) {
        uint32_t raw[HV];
        ld_row<HV>(X + (size_t)col[j] * F, lane, raw);
#pragma unroll
        for (int v = 0; v < HV; v++) {
            float2 f = __half22float2(*(__half2*)&raw[v]);
            acc[0][v].x += f.x; acc[0][v].y += f.y;
        }
    }
    float inv = (e > s) ? 1.0f / (float)(e - s) : 0.0f;
    uint32_t o[HV];
#pragma unroll
    for (int v = 0; v < HV; v++) {
        float2 m;
        m.x = (acc[0][v].x + acc[1][v].x + acc[2][v].x + acc[3][v].x) * inv;
        m.y = (acc[0][v].y + acc[1][v].y + acc[2][v].y + acc[3][v].y) * inv;
        __half2 h = __float22half2_rn(m);
        o[v] = *(uint32_t*)&h;
    }
    __half* orow = out + (size_t)w * F;
    if constexpr (HV == 4) ((uint4*)orow)[lane] = make_uint4(o[0], o[1], o[2], o[3]);
    else if constexpr (HV == 2) ((uint2*)orow)[lane] = make_uint2(o[0], o[1]);
    else ((uint32_t*)orow)[lane] = o[0];
}

template <int HV>
__global__ __launch_bounds__(256) void agg_kernel(const __half* __restrict__ X,
                                                  const int* __restrict__ rs,
                                                  const int* __restrict__ col,
                                                  __half* __restrict__ out, int ndst) {
    int w = blockIdx.x * 8 + (threadIdx.x >> 5);
    int lane = threadIdx.x & 31;
    if (w < ndst) agg_body_h<HV>(X, rs, col, out, w, lane);
}

// ================= fp16 mma.sync dual-A GEMM, cp.async 3-stage =================
#define HROW_B    80
#define HSTAGE_A  (128 * HROW_B)           // 10240
#define HSTAGE    (2 * HSTAGE_A)           // 20480
#define NSTAGE    3
#define HGEMM_SMEM (NSTAGE * HSTAGE)       // 61440

struct GemmSideH {
    const __half *A1, *W1, *A2, *W2;
    const float* bias;
    void* C;
    int K1, K2, M;
};

__device__ __forceinline__ uint32_t smem_u32(const void* p) {
    uint32_t a;
    asm("{ .reg .u64 t; cvta.to.shared.u64 t, %1; cvt.u32.u64 %0, t; }" : "=r"(a) : "l"(p));
    return a;
}

__device__ __forceinline__ void ldsm_x4(uint32_t* r, uint32_t addr) {
    asm volatile("ldmatrix.sync.aligned.m8n8.x4.shared.b16 {%0,%1,%2,%3}, [%4];"
                 : "=r"(r[0]), "=r"(r[1]), "=r"(r[2]), "=r"(r[3]) : "r"(addr));
}

__device__ __forceinline__ void mma_f16(float* d, const uint32_t* a, uint32_t b0, uint32_t b1) {
    asm volatile(
        "mma.sync.aligned.m16n8k16.row.col.f32.f16.f16.f32 "
        "{%0,%1,%2,%3}, {%4,%5,%6,%7}, {%8,%9}, {%0,%1,%2,%3};"
        : "+f"(d[0]), "+f"(d[1]), "+f"(d[2]), "+f"(d[3])
        : "r"(a[0]), "r"(a[1]), "r"(a[2]), "r"(a[3]), "r"(b0), "r"(b1));
}

__device__ __forceinline__ void cp_async16(uint32_t smem, const void* g, bool pred) {
    int sz = pred ? 16 : 0;
    asm volatile("cp.async.cg.shared.global [%0], [%1], 16, %2;"
                 :: "r"(smem), "l"(g), "r"(sz) : "memory");
}
#define CP_COMMIT() asm volatile("cp.async.commit_group;" ::: "memory")
#define CP_WAIT1()  asm volatile("cp.async.wait_group 1;" ::: "memory")

template <bool RELU, typename CT>
__global__ __launch_bounds__(256, 2) void gemm_h_fused(GemmSideH sa, GemmSideH sb, int mblk_a) {
    extern __shared__ __align__(16) char dsmem[];
    const uint32_t sm0 = smem_u32(dsmem);

    const bool sideA = (int)blockIdx.x < mblk_a;
    const __half* A1 = sideA ? sa.A1 : sb.A1;
    const __half* W1 = sideA ? sa.W1 : sb.W1;
    const __half* A2 = sideA ? sa.A2 : sb.A2;
    const __half* W2 = sideA ? sa.W2 : sb.W2;
    const float* bias = sideA ? sa.bias : sb.bias;
    CT* C = (CT*)(sideA ? sa.C : sb.C);
    const int K1 = sideA ? sa.K1 : sb.K1;
    const int K2 = sideA ? sa.K2 : sb.K2;
    const int M  = sideA ? sa.M  : sb.M;
    const int mb = sideA ? blockIdx.x : blockIdx.x - mblk_a;

    const int tid = threadIdx.x;
    const int wid = tid >> 5;
    const int lane = tid & 31;
    const int warp_m = wid >> 2;
    const int warp_n = wid & 3;
    const int m0 = mb * 128;
    const int n0 = blockIdx.y * 128;

    const int row0 = tid >> 2;
    const int cc8 = (tid & 3) * 8;
    const uint32_t stoff = (uint32_t)(row0 * HROW_B + (tid & 3) * 16);

    float acc[4][4][4];
#pragma unroll
    for (int i = 0; i < 4; i++)
#pragma unroll
        for (int j = 0; j < 4; j++)
#pragma unroll
            for (int k = 0; k < 4; k++) acc[i][j][k] = 0.f;

    const int n1 = K1 / 32;
    const int n2 = K2 / 32;
    const int T = n1 + n2;

    auto issue_g = [&](int it, int slot) {
        const __half* A; const __half* W; int K, k0;
        if (it < n1) { A = A1; W = W1; K = K1; k0 = it * 32; }
        else         { A = A2; W = W2; K = K2; k0 = (it - n1) * 32; }
        const int cc = k0 + cc8;
        const uint32_t bA = sm0 + slot * HSTAGE;
        const uint32_t bB = bA + HSTAGE_A;
#pragma unroll
        for (int q = 0; q < 2; q++) {
            const int r = row0 + 64 * q;
            cp_async16(bA + stoff + (uint32_t)(64 * q * HROW_B),
                       A + (size_t)(m0 + r) * K + cc, m0 + r < M);
            cp_async16(bB + stoff + (uint32_t)(64 * q * HROW_B),
                       W + (size_t)(n0 + r) * K + cc, true);
        }
    };

    const int rowsel = (lane & 7) | (((lane >> 3) & 1) << 3);
    const int colsel = (lane >> 4) * 16;

    auto compute_s = [&](int st) {
        const uint32_t bA = sm0 + st * HSTAGE;
        const uint32_t bB = bA + HSTAGE_A;
        const uint32_t aBase = bA + (uint32_t)((warp_m * 64 + rowsel) * HROW_B + colsel);
        const uint32_t bBase = bB + (uint32_t)((warp_n * 32 + rowsel) * HROW_B + colsel);
#pragma unroll
        for (int ks = 0; ks < 2; ks++) {
            const uint32_t ko = ks * 32;
            uint32_t af[4][4], bf[8];
#pragma unroll
            for (int i = 0; i < 4; i++)
                ldsm_x4(af[i], aBase + i * (16 * HROW_B) + ko);
            ldsm_x4(bf + 0, bBase + ko);
            ldsm_x4(bf + 4, bBase + 16 * HROW_B + ko);
#pragma unroll
            for (int i = 0; i < 4; i++)
#pragma unroll
                for (int j = 0; j < 4; j++) {
                    const int bi = (j >> 1) * 4 + (j & 1);
                    mma_f16(acc[i][j], af[i], bf[bi], bf[bi + 2]);
                }
        }
    };

    issue_g(0, 0);
    CP_COMMIT();
    if (T > 1) issue_g(1, 1);
    CP_COMMIT();
    CP_WAIT1();
    __syncthreads();

    int slot = 0;
#pragma unroll 1
    for (int it = 0; it < T; it++) {
        compute_s(slot);
        if (it + 2 < T) issue_g(it + 2, (it + 2) % NSTAGE);
        CP_COMMIT();
        CP_WAIT1();
        __syncthreads();
        slot = (slot + 1 == NSTAGE) ? 0 : slot + 1;
    }

    const int g = lane >> 2;
    const int t = lane & 3;
#pragma unroll
    for (int j = 0; j < 4; j++) {
        const int nb = n0 + warp_n * 32 + j * 8 + t * 2;
        const float bx = bias[nb], by = bias[nb + 1];
#pragma unroll
        for (int i = 0; i < 4; i++) {
            const int rlo = m0 + warp_m * 64 + i * 16 + g;
            if (rlo < M) {
                float vx = acc[i][j][0] + bx, vy = acc[i][j][1] + by;
                if (RELU) { vx = fmaxf(vx, 0.f); vy = fmaxf(vy, 0.f); }
                if constexpr (sizeof(CT) == 2) {
                    __half2 hv = __float22half2_rn(make_float2(vx, vy));
                    *(__half2*)((__half*)C + (size_t)rlo * HH + nb) = hv;
                } else {
                    *(float2*)((float*)C + (size_t)rlo * HH + nb) = make_float2(vx, vy);
                }
            }
            const int rhi = rlo + 8;
            if (rhi < M) {
                float vx = acc[i][j][2] + bx, vy = acc[i][j][3] + by;
                if (RELU) { vx = fmaxf(vx, 0.f); vy = fmaxf(vy, 0.f); }
                if constexpr (sizeof(CT) == 2) {
                    __half2 hv = __float22half2_rn(make_float2(vx, vy));
                    *(__half2*)((__half*)C + (size_t)rhi * HH + nb) = hv;
                } else {
                    *(float2*)((float*)C + (size_t)rhi * HH + nb) = make_float2(vx, vy);
                }
            }
        }
    }
}

// ---------------- host ----------------
extern "C" void kernel_launch(void* const* d_in, const int* in_sizes, int n_in,
                              void* d_out, int out_size) {
    const float* x_user = (const float*)d_in[0];
    const float* x_item = (const float*)d_in[1];
    const int* ui_src = (const int*)d_in[2];
    const int* ui_dst = (const int*)d_in[3];
    const int* iu_src = (const int*)d_in[4];
    const int* iu_dst = (const int*)d_in[5];
    const float* W1l_ui = (const float*)d_in[6];
    const float* b1_ui  = (const float*)d_in[7];
    const float* W1r_ui = (const float*)d_in[8];
    const float* W1l_iu = (const float*)d_in[9];
    const float* b1_iu  = (const float*)d_in[10];
    const float* W1r_iu = (const float*)d_in[11];
    const float* W2l_ui = (const float*)d_in[12];
    const float* b2_ui  = (const float*)d_in[13];
    const float* W2r_ui = (const float*)d_in[14];
    const float* W2l_iu = (const float*)d_in[15];
    const float* b2_iu  = (const float*)d_in[16];
    const float* W2r_iu = (const float*)d_in[17];

    int *cnt_item, *cnt_user, *cur_item, *cur_user, *rs_item, *rs_user, *col_ui, *col_iu;
    unsigned int* tkt;
    unsigned long long* desc;
    __half *xu_h, *xi_h, *agg_item_h, *agg_user_h, *h_item_h, *h_user_h,
           *aggH_item_h, *aggH_user_h, *w_h;
    cudaGetSymbolAddress((void**)&cnt_item, g_cnt_item);
    cudaGetSymbolAddress((void**)&cnt_user, g_cnt_user);
    cudaGetSymbolAddress((void**)&cur_item, g_cur_item);
    cudaGetSymbolAddress((void**)&cur_user, g_cur_user);
    cudaGetSymbolAddress((void**)&rs_item, g_rs_item);
    cudaGetSymbolAddress((void**)&rs_user, g_rs_user);
    cudaGetSymbolAddress((void**)&col_ui, g_col_ui);
    cudaGetSymbolAddress((void**)&col_iu, g_col_iu);
    cudaGetSymbolAddress((void**)&tkt, g_tkt);
    cudaGetSymbolAddress((void**)&desc, g_desc);
    cudaGetSymbolAddress((void**)&xu_h, g_xu_h);
    cudaGetSymbolAddress((void**)&xi_h, g_xi_h);
    cudaGetSymbolAddress((void**)&agg_item_h, g_agg_item_h);
    cudaGetSymbolAddress((void**)&agg_user_h, g_agg_user_h);
    cudaGetSymbolAddress((void**)&h_item_h, g_h_item_h);
    cudaGetSymbolAddress((void**)&h_user_h, g_h_user_h);
    cudaGetSymbolAddress((void**)&aggH_item_h, g_aggH_item_h);
    cudaGetSymbolAddress((void**)&aggH_user_h, g_aggH_user_h);
    cudaGetSymbolAddress((void**)&w_h, g_w_h);

    cudaFuncSetAttribute(gemm_h_fused<true, __half>,
                         cudaFuncAttributeMaxDynamicSharedMemorySize, HGEMM_SMEM);
    cudaFuncSetAttribute(gemm_h_fused<false, float>,
                         cudaFuncAttributeMaxDynamicSharedMemorySize, HGEMM_SMEM);

    static cudaStream_t s2 = [] {
        cudaStream_t s; cudaStreamCreateWithFlags(&s, cudaStreamNonBlocking); return s;
    }();
    auto mkev = [] { cudaEvent_t e; cudaEventCreateWithFlags(&e, cudaEventDisableTiming); return e; };
    static cudaEvent_t evFork = mkev();
    static cudaEvent_t evCvt  = mkev();
    static cudaEvent_t evScan = mkev();
    static cudaEvent_t evHuser = mkev();
    static cudaEvent_t evA2i  = mkev();
    static cudaEvent_t evDone = mkev();

    // ---- fork: cvt on s2 (overlaps CSR build) ----
    cudaEventRecord(evFork, 0);
    cudaStreamWaitEvent(s2, evFork, 0);
    {
        CvtArgs a;
        a.seg[0] = { x_user, xu_h, (N_USERC * DU) / 4 };
        a.seg[1] = { x_item, xi_h, (N_ITEMC * DI) / 4 };
        a.seg[2] = { W1l_ui, w_h + O_W1L_UI, (HH * DU) / 4 };
        a.seg[3] = { W1r_ui, w_h + O_W1R_UI, (HH * DI) / 4 };
        a.seg[4] = { W1l_iu, w_h + O_W1L_IU, (HH * DI) / 4 };
        a.seg[5] = { W1r_iu, w_h + O_W1R_IU, (HH * DU) / 4 };
        a.seg[6] = { W2l_ui, w_h + O_W2L_UI, (HH * HH) / 4 };
        a.seg[7] = { W2r_ui, w_h + O_W2R_UI, (HH * HH) / 4 };
        a.seg[8] = { W2l_iu, w_h + O_W2L_IU, (HH * HH) / 4 };
        a.seg[9] = { W2r_iu, w_h + O_W2R_IU, (HH * HH) / 4 };
        cvt_kernel<<<1024, 256, 0, s2>>>(a);
    }
    cudaEventRecord(evCvt, s2);

    // ---- CSR head on stream 0 ----
    cudaMemsetAsync(cnt_item, 0, N_ITEMC * sizeof(int), 0);
    cudaMemsetAsync(cnt_user, 0, N_USERC * sizeof(int), 0);
    cudaMemsetAsync(tkt, 0, 2 * sizeof(unsigned int), 0);
    cudaMemsetAsync(desc, 0, 2 * 160 * sizeof(unsigned long long), 0);
    count_kernel<<<(NE / 4 + 255) / 256, 256>>>(ui_dst, iu_dst);
    scan_lookback_kernel<<<dim3(98, 2), 256>>>();
    cudaEventRecord(evScan, 0);

    // ---- item chain on s0: fill_item -> aggL1_item -> gemm1_item ----
    fill_side_kernel<<<(NE / 4 + 255) / 256, 256>>>(ui_src, ui_dst, cur_item, col_ui);
    cudaStreamWaitEvent(0, evCvt, 0);
    agg_kernel<2><<<AGG_BLK_ITEM, 256>>>(xu_h, rs_item, col_ui, agg_item_h, N_ITEMC);
    {
        GemmSideH si = { agg_item_h, w_h + O_W1L_UI, xi_h, w_h + O_W1R_UI,
                         b1_ui, h_item_h, DU, DI, N_ITEMC };
        gemm_h_fused<true, __half><<<dim3(MBLK_ITEM, 2), 256, HGEMM_SMEM>>>(si, si, MBLK_ITEM);
    }

    // ---- user chain on s2: fill_user -> aggL1_user -> gemm1_user ----
    cudaStreamWaitEvent(s2, evScan, 0);
    fill_side_kernel<<<(NE / 4 + 255) / 256, 256, 0, s2>>>(iu_src, iu_dst, cur_user, col_iu);
    agg_kernel<1><<<AGG_BLK_USER, 256, 0, s2>>>(xi_h, rs_user, col_iu, agg_user_h, N_USERC);
    {
        GemmSideH su = { agg_user_h, w_h + O_W1L_IU, xu_h, w_h + O_W1R_IU,
                         b1_iu, h_user_h, DI, DU, N_USERC };
        gemm_h_fused<true, __half><<<dim3(MBLK_USER, 2), 256, HGEMM_SMEM, s2>>>(su, su, MBLK_USER);
    }
    cudaEventRecord(evHuser, s2);

    float* out_user = (float*)d_out;
    float* out_item = out_user + (size_t)N_USERC * HH;

    // ---- layer 2, staggered: aggL2_item first (s0), then gemm2_item (tensor)
    //      runs concurrently with aggL2_user (LTS) on s2 ----
    cudaStreamWaitEvent(0, evHuser, 0);
    agg_kernel<4><<<AGG_BLK_ITEM, 256>>>(h_user_h, rs_item, col_ui, aggH_item_h, N_ITEMC);
    cudaEventRecord(evA2i, 0);
    {
        GemmSideH si = { aggH_item_h, w_h + O_W2L_UI, h_item_h, w_h + O_W2R_UI,
                         b2_ui, out_item, HH, HH, N_ITEMC };
        gemm_h_fused<false, float><<<dim3(MBLK_ITEM, 2), 256, HGEMM_SMEM>>>(si, si, MBLK_ITEM);
    }

    cudaStreamWaitEvent(s2, evA2i, 0);
    agg_kernel<4><<<AGG_BLK_USER, 256, 0, s2>>>(h_item_h, rs_user, col_iu, aggH_user_h, N_USERC);
    {
        GemmSideH su = { aggH_user_h, w_h + O_W2L_IU, h_user_h, w_h + O_W2R_IU,
                         b2_iu, out_user, HH, HH, N_USERC };
        gemm_h_fused<false, float><<<dim3(MBLK_USER, 2), 256, HGEMM_SMEM, s2>>>(su, su, MBLK_USER);
    }
    cudaEventRecord(evDone, s2);

    // ---- final join back to the capture stream ----
    cudaStreamWaitEvent(0, evDone, 0);
}

// round 16
// speedup vs baseline: 1.5853x; 1.0073x over previous
#include <cuda_runtime.h>
#include <cuda_fp16.h>
#include <cstdint>

#define N_USERC 100000
#define N_ITEMC 50000
#define NE      1600000
#define DU      128
#define DI      64
#define HH      256

#define AGG_BLK_ITEM ((N_ITEMC + 7) / 8)     // 6250
#define AGG_BLK_USER ((N_USERC + 7) / 8)     // 12500
#define MBLK_ITEM ((N_ITEMC + 127) / 128)    // 391
#define MBLK_USER ((N_USERC + 127) / 128)    // 782

// ---------------- device scratch ----------------
__device__ __align__(16) int g_cnt_item[N_ITEMC];
__device__ __align__(16) int g_cnt_user[N_USERC];
__device__ __align__(16) int g_cur_item[N_ITEMC];   // seeded with rs (write cursors)
__device__ __align__(16) int g_cur_user[N_USERC];
__device__ __align__(16) int g_rs_item[N_ITEMC + 1];
__device__ __align__(16) int g_rs_user[N_USERC + 1];
__device__ __align__(16) int g_col_ui[NE];
__device__ __align__(16) int g_col_iu[NE];

__device__ unsigned int g_tkt[2];
__device__ __align__(16) unsigned long long g_desc[2][160];

__device__ __align__(128) __half g_xu_h[(size_t)N_USERC * DU];
__device__ __align__(128) __half g_xi_h[(size_t)N_ITEMC * DI];
__device__ __align__(128) __half g_agg_item_h[(size_t)N_ITEMC * DU];
__device__ __align__(128) __half g_agg_user_h[(size_t)N_USERC * DI];
__device__ __align__(128) __half g_h_item_h[(size_t)N_ITEMC * HH];
__device__ __align__(128) __half g_h_user_h[(size_t)N_USERC * HH];
__device__ __align__(128) __half g_aggH_item_h[(size_t)N_ITEMC * HH];
__device__ __align__(128) __half g_aggH_user_h[(size_t)N_USERC * HH];
__device__ __align__(128) __half g_w_h[360448];

// weight offsets in g_w_h
#define O_W1L_UI 0
#define O_W1R_UI 32768
#define O_W1L_IU 49152
#define O_W1R_IU 65536
#define O_W2L_UI 98304
#define O_W2R_UI 163840
#define O_W2L_IU 229376
#define O_W2R_IU 294912

// ---------------- fp32 -> fp16 convert ----------------
struct CvtSeg { const float* s; __half* d; int n4; };
struct CvtArgs { CvtSeg seg[10]; };

__global__ void cvt_kernel(CvtArgs args) {
    const int gid = blockIdx.x * blockDim.x + threadIdx.x;
    const int stride = gridDim.x * blockDim.x;
#pragma unroll 1
    for (int k = 0; k < 10; k++) {
        CvtSeg g = args.seg[k];
        for (int i = gid; i < g.n4; i += stride) {
            float4 v = __ldg((const float4*)g.s + i);
            __half2 h0 = __float22half2_rn(make_float2(v.x, v.y));
            __half2 h1 = __float22half2_rn(make_float2(v.z, v.w));
            uint2 o;
            o.x = *(uint32_t*)&h0;
            o.y = *(uint32_t*)&h1;
            ((uint2*)g.d)[i] = o;
        }
    }
}

// ---------------- per-side CSR build ----------------
__global__ void count_side_kernel(const int* __restrict__ dst, int* __restrict__ cnt) {
    int i = blockIdx.x * blockDim.x + threadIdx.x;
    if (i >= NE / 4) return;
    int4 a = __ldg((const int4*)dst + i);
    atomicAdd(&cnt[a.x], 1); atomicAdd(&cnt[a.y], 1);
    atomicAdd(&cnt[a.z], 1); atomicAdd(&cnt[a.w], 1);
}

// per-side decoupled-lookback scan; seeds cur with rs
__global__ void scan_side_kernel(int y) {
    const int* __restrict__ cnt = y == 0 ? g_cnt_item : g_cnt_user;
    int* __restrict__ rs  = y == 0 ? g_rs_item  : g_rs_user;
    int* __restrict__ cur = y == 0 ? g_cur_item : g_cur_user;
    const int n = y == 0 ? N_ITEMC : N_USERC;
    const int nblk = (n + 1023) / 1024;
    if ((int)blockIdx.x >= nblk) return;

    __shared__ int s_vb;
    __shared__ int s_wsum[8];
    __shared__ int s_run;
    const int tid = threadIdx.x, lane = tid & 31, wid = tid >> 5;

    if (tid == 0) s_vb = atomicAdd(&g_tkt[y], 1u);
    __syncthreads();
    const int vb = s_vb;
    const int base = vb * 1024 + tid * 4;

    int v0 = 0, v1 = 0, v2 = 0, v3 = 0;
    if (base + 3 < n) {
        v0 = cnt[base]; v1 = cnt[base + 1]; v2 = cnt[base + 2]; v3 = cnt[base + 3];
    } else {
        if (base     < n) v0 = cnt[base];
        if (base + 1 < n) v1 = cnt[base + 1];
        if (base + 2 < n) v2 = cnt[base + 2];
        if (base + 3 < n) v3 = cnt[base + 3];
    }
    const int tot = v0 + v1 + v2 + v3;
    int inc = tot;
#pragma unroll
    for (int o = 1; o < 32; o <<= 1) {
        int u = __shfl_up_sync(0xffffffffu, inc, o);
        if (lane >= o) inc += u;
    }
    if (lane == 31) s_wsum[wid] = inc;
    __syncthreads();
    if (wid == 0) {
        int w = (lane < 8) ? s_wsum[lane] : 0;
#pragma unroll
        for (int o = 1; o < 8; o <<= 1) {
            int u = __shfl_up_sync(0xffffffffu, w, o);
            if (lane >= o) w += u;
        }
        if (lane < 8) s_wsum[lane] = w;
    }
    __syncthreads();
    const int agg = s_wsum[7];
    const int thr_exc = (wid ? s_wsum[wid - 1] : 0) + inc - tot;

    if (tid == 0) {
        if (vb == 0) {
            atomicExch(&g_desc[y][0], (2ull << 32) | (unsigned)agg);
            s_run = 0;
        } else {
            atomicExch(&g_desc[y][vb], (1ull << 32) | (unsigned)agg);
            int run = 0, p = vb - 1;
            while (true) {
                unsigned long long d;
                do { d = atomicAdd(&g_desc[y][p], 0ull); } while ((d >> 32) == 0ull);
                run += (int)(d & 0xffffffffull);
                if ((d >> 32) == 2ull) break;
                p--;
            }
            atomicExch(&g_desc[y][vb], (2ull << 32) | (unsigned)(run + agg));
            s_run = run;
        }
    }
    __syncthreads();
    const int run = s_run;
    const int e0 = run + thr_exc;
    if (base     < n) { int v = e0;                rs[base]     = v; cur[base]     = v; }
    if (base + 1 < n) { int v = e0 + v0;           rs[base + 1] = v; cur[base + 1] = v; }
    if (base + 2 < n) { int v = e0 + v0 + v1;      rs[base + 2] = v; cur[base + 2] = v; }
    if (base + 3 < n) { int v = e0 + v0 + v1 + v2; rs[base + 3] = v; cur[base + 3] = v; }
    if (vb == nblk - 1 && tid == 0) rs[n] = run + agg;
}

// per-side fill: single atomic per edge (cursor pre-seeded with row start)
__global__ void fill_side_kernel(const int* __restrict__ src, const int* __restrict__ dst,
                                 int* __restrict__ cur, int* __restrict__ col) {
    int i = blockIdx.x * blockDim.x + threadIdx.x;
    if (i >= NE / 4) return;
    int4 s4 = __ldg((const int4*)src + i);
    int4 d4 = __ldg((const int4*)dst + i);
    int p0 = atomicAdd(&cur[d4.x], 1);
    int p1 = atomicAdd(&cur[d4.y], 1);
    int p2 = atomicAdd(&cur[d4.z], 1);
    int p3 = atomicAdd(&cur[d4.w], 1);
    col[p0] = s4.x;
    col[p1] = s4.y;
    col[p2] = s4.z;
    col[p3] = s4.w;
}

// ---------------- fp16 gather-based segment mean ----------------
template <int HV>
__device__ __forceinline__ void ld_row(const __half* p, int lane, uint32_t* raw) {
    if constexpr (HV == 4) {
        uint4 t = __ldg((const uint4*)p + lane);
        raw[0] = t.x; raw[1] = t.y; raw[2] = t.z; raw[3] = t.w;
    } else if constexpr (HV == 2) {
        uint2 t = __ldg((const uint2*)p + lane);
        raw[0] = t.x; raw[1] = t.y;
    } else {
        raw[0] = __ldg((const uint32_t*)p + lane);
    }
}

template <int HV>
__device__ __forceinline__ void agg_body_h(const __half* __restrict__ X,
                                           const int* __restrict__ rs,
                                           const int* __restrict__ col,
                                           __half* __restrict__ out, int w, int lane) {
    const int F = HV * 64;
    int s = rs[w], e = rs[w + 1];
    float2 acc[4][HV];
#pragma unroll
    for (int u = 0; u < 4; u++)
#pragma unroll
        for (int v = 0; v < HV; v++) acc[u][v] = make_float2(0.f, 0.f);

    int j = s;
    for (; j + 3 < e; j += 4) {
        uint32_t raw[4][HV];
#pragma unroll
        for (int u = 0; u < 4; u++)
            ld_row<HV>(X + (size_t)col[j + u] * F, lane, raw[u]);
#pragma unroll
        for (int u = 0; u < 4; u++)
#pragma unroll
            for (int v = 0; v < HV; v++) {
                float2 f = __half22float2(*(__half2*)&raw[u][v]);
                acc[u][v].x += f.x; acc[u][v].y += f.y;
            }
    }
    for (; j < e; j++) {
        uint32_t raw[HV];
        ld_row<HV>(X + (size_t)col[j] * F, lane, raw);
#pragma unroll
        for (int v = 0; v < HV; v++) {
            float2 f = __half22float2(*(__half2*)&raw[v]);
            acc[0][v].x += f.x; acc[0][v].y += f.y;
        }
    }
    float inv = (e > s) ? 1.0f / (float)(e - s) : 0.0f;
    uint32_t o[HV];
#pragma unroll
    for (int v = 0; v < HV; v++) {
        float2 m;
        m.x = (acc[0][v].x + acc[1][v].x + acc[2][v].x + acc[3][v].x) * inv;
        m.y = (acc[0][v].y + acc[1][v].y + acc[2][v].y + acc[3][v].y) * inv;
        __half2 h = __float22half2_rn(m);
        o[v] = *(uint32_t*)&h;
    }
    __half* orow = out + (size_t)w * F;
    if constexpr (HV == 4) ((uint4*)orow)[lane] = make_uint4(o[0], o[1], o[2], o[3]);
    else if constexpr (HV == 2) ((uint2*)orow)[lane] = make_uint2(o[0], o[1]);
    else ((uint32_t*)orow)[lane] = o[0];
}

template <int HV>
__global__ __launch_bounds__(256) void agg_kernel(const __half* __restrict__ X,
                                                  const int* __restrict__ rs,
                                                  const int* __restrict__ col,
                                                  __half* __restrict__ out, int ndst) {
    int w = blockIdx.x * 8 + (threadIdx.x >> 5);
    int lane = threadIdx.x & 31;
    if (w < ndst) agg_body_h<HV>(X, rs, col, out, w, lane);
}

// ================= fp16 mma.sync dual-A GEMM, cp.async 3-stage =================
#define HROW_B    80
#define HSTAGE_A  (128 * HROW_B)           // 10240
#define HSTAGE    (2 * HSTAGE_A)           // 20480
#define NSTAGE    3
#define HGEMM_SMEM (NSTAGE * HSTAGE)       // 61440

struct GemmSideH {
    const __half *A1, *W1, *A2, *W2;
    const float* bias;
    void* C;
    int K1, K2, M;
};

__device__ __forceinline__ uint32_t smem_u32(const void* p) {
    uint32_t a;
    asm("{ .reg .u64 t; cvta.to.shared.u64 t, %1; cvt.u32.u64 %0, t; }" : "=r"(a) : "l"(p));
    return a;
}

__device__ __forceinline__ void ldsm_x4(uint32_t* r, uint32_t addr) {
    asm volatile("ldmatrix.sync.aligned.m8n8.x4.shared.b16 {%0,%1,%2,%3}, [%4];"
                 : "=r"(r[0]), "=r"(r[1]), "=r"(r[2]), "=r"(r[3]) : "r"(addr));
}

__device__ __forceinline__ void mma_f16(float* d, const uint32_t* a, uint32_t b0, uint32_t b1) {
    asm volatile(
        "mma.sync.aligned.m16n8k16.row.col.f32.f16.f16.f32 "
        "{%0,%1,%2,%3}, {%4,%5,%6,%7}, {%8,%9}, {%0,%1,%2,%3};"
        : "+f"(d[0]), "+f"(d[1]), "+f"(d[2]), "+f"(d[3])
        : "r"(a[0]), "r"(a[1]), "r"(a[2]), "r"(a[3]), "r"(b0), "r"(b1));
}

__device__ __forceinline__ void cp_async16(uint32_t smem, const void* g, bool pred) {
    int sz = pred ? 16 : 0;
    asm volatile("cp.async.cg.shared.global [%0], [%1], 16, %2;"
                 :: "r"(smem), "l"(g), "r"(sz) : "memory");
}
#define CP_COMMIT() asm volatile("cp.async.commit_group;" ::: "memory")
#define CP_WAIT1()  asm volatile("cp.async.wait_group 1;" ::: "memory")

template <bool RELU, typename CT>
__global__ __launch_bounds__(256, 2) void gemm_h_fused(GemmSideH sa, GemmSideH sb, int mblk_a) {
    extern __shared__ __align__(16) char dsmem[];
    const uint32_t sm0 = smem_u32(dsmem);

    const bool sideA = (int)blockIdx.x < mblk_a;
    const __half* A1 = sideA ? sa.A1 : sb.A1;
    const __half* W1 = sideA ? sa.W1 : sb.W1;
    const __half* A2 = sideA ? sa.A2 : sb.A2;
    const __half* W2 = sideA ? sa.W2 : sb.W2;
    const float* bias = sideA ? sa.bias : sb.bias;
    CT* C = (CT*)(sideA ? sa.C : sb.C);
    const int K1 = sideA ? sa.K1 : sb.K1;
    const int K2 = sideA ? sa.K2 : sb.K2;
    const int M  = sideA ? sa.M  : sb.M;
    const int mb = sideA ? blockIdx.x : blockIdx.x - mblk_a;

    const int tid = threadIdx.x;
    const int wid = tid >> 5;
    const int lane = tid & 31;
    const int warp_m = wid >> 2;
    const int warp_n = wid & 3;
    const int m0 = mb * 128;
    const int n0 = blockIdx.y * 128;

    const int row0 = tid >> 2;
    const int cc8 = (tid & 3) * 8;
    const uint32_t stoff = (uint32_t)(row0 * HROW_B + (tid & 3) * 16);

    float acc[4][4][4];
#pragma unroll
    for (int i = 0; i < 4; i++)
#pragma unroll
        for (int j = 0; j < 4; j++)
#pragma unroll
            for (int k = 0; k < 4; k++) acc[i][j][k] = 0.f;

    const int n1 = K1 / 32;
    const int n2 = K2 / 32;
    const int T = n1 + n2;

    auto issue_g = [&](int it, int slot) {
        const __half* A; const __half* W; int K, k0;
        if (it < n1) { A = A1; W = W1; K = K1; k0 = it * 32; }
        else         { A = A2; W = W2; K = K2; k0 = (it - n1) * 32; }
        const int cc = k0 + cc8;
        const uint32_t bA = sm0 + slot * HSTAGE;
        const uint32_t bB = bA + HSTAGE_A;
#pragma unroll
        for (int q = 0; q < 2; q++) {
            const int r = row0 + 64 * q;
            cp_async16(bA + stoff + (uint32_t)(64 * q * HROW_B),
                       A + (size_t)(m0 + r) * K + cc, m0 + r < M);
            cp_async16(bB + stoff + (uint32_t)(64 * q * HROW_B),
                       W + (size_t)(n0 + r) * K + cc, true);
        }
    };

    const int rowsel = (lane & 7) | (((lane >> 3) & 1) << 3);
    const int colsel = (lane >> 4) * 16;

    auto compute_s = [&](int st) {
        const uint32_t bA = sm0 + st * HSTAGE;
        const uint32_t bB = bA + HSTAGE_A;
        const uint32_t aBase = bA + (uint32_t)((warp_m * 64 + rowsel) * HROW_B + colsel);
        const uint32_t bBase = bB + (uint32_t)((warp_n * 32 + rowsel) * HROW_B + colsel);
#pragma unroll
        for (int ks = 0; ks < 2; ks++) {
            const uint32_t ko = ks * 32;
            uint32_t af[4][4], bf[8];
#pragma unroll
            for (int i = 0; i < 4; i++)
                ldsm_x4(af[i], aBase + i * (16 * HROW_B) + ko);
            ldsm_x4(bf + 0, bBase + ko);
            ldsm_x4(bf + 4, bBase + 16 * HROW_B + ko);
#pragma unroll
            for (int i = 0; i < 4; i++)
#pragma unroll
                for (int j = 0; j < 4; j++) {
                    const int bi = (j >> 1) * 4 + (j & 1);
                    mma_f16(acc[i][j], af[i], bf[bi], bf[bi + 2]);
                }
        }
    };

    issue_g(0, 0);
    CP_COMMIT();
    if (T > 1) issue_g(1, 1);
    CP_COMMIT();
    CP_WAIT1();
    __syncthreads();

    int slot = 0;
#pragma unroll 1
    for (int it = 0; it < T; it++) {
        compute_s(slot);
        if (it + 2 < T) issue_g(it + 2, (it + 2) % NSTAGE);
        CP_COMMIT();
        CP_WAIT1();
        __syncthreads();
        slot = (slot + 1 == NSTAGE) ? 0 : slot + 1;
    }

    const int g = lane >> 2;
    const int t = lane & 3;
#pragma unroll
    for (int j = 0; j < 4; j++) {
        const int nb = n0 + warp_n * 32 + j * 8 + t * 2;
        const float bx = bias[nb], by = bias[nb + 1];
#pragma unroll
        for (int i = 0; i < 4; i++) {
            const int rlo = m0 + warp_m * 64 + i * 16 + g;
            if (rlo < M) {
                float vx = acc[i][j][0] + bx, vy = acc[i][j][1] + by;
                if (RELU) { vx = fmaxf(vx, 0.f); vy = fmaxf(vy, 0.f); }
                if constexpr (sizeof(CT) == 2) {
                    __half2 hv = __float22half2_rn(make_float2(vx, vy));
                    *(__half2*)((__half*)C + (size_t)rlo * HH + nb) = hv;
                } else {
                    *(float2*)((float*)C + (size_t)rlo * HH + nb) = make_float2(vx, vy);
                }
            }
            const int rhi = rlo + 8;
            if (rhi < M) {
                float vx = acc[i][j][2] + bx, vy = acc[i][j][3] + by;
                if (RELU) { vx = fmaxf(vx, 0.f); vy = fmaxf(vy, 0.f); }
                if constexpr (sizeof(CT) == 2) {
                    __half2 hv = __float22half2_rn(make_float2(vx, vy));
                    *(__half2*)((__half*)C + (size_t)rhi * HH + nb) = hv;
                } else {
                    *(float2*)((float*)C + (size_t)rhi * HH + nb) = make_float2(vx, vy);
                }
            }
        }
    }
}

// ---------------- host ----------------
extern "C" void kernel_launch(void* const* d_in, const int* in_sizes, int n_in,
                              void* d_out, int out_size) {
    const float* x_user = (const float*)d_in[0];
    const float* x_item = (const float*)d_in[1];
    const int* ui_src = (const int*)d_in[2];
    const int* ui_dst = (const int*)d_in[3];
    const int* iu_src = (const int*)d_in[4];
    const int* iu_dst = (const int*)d_in[5];
    const float* W1l_ui = (const float*)d_in[6];
    const float* b1_ui  = (const float*)d_in[7];
    const float* W1r_ui = (const float*)d_in[8];
    const float* W1l_iu = (const float*)d_in[9];
    const float* b1_iu  = (const float*)d_in[10];
    const float* W1r_iu = (const float*)d_in[11];
    const float* W2l_ui = (const float*)d_in[12];
    const float* b2_ui  = (const float*)d_in[13];
    const float* W2r_ui = (const float*)d_in[14];
    const float* W2l_iu = (const float*)d_in[15];
    const float* b2_iu  = (const float*)d_in[16];
    const float* W2r_iu = (const float*)d_in[17];

    int *cnt_item, *cnt_user, *cur_item, *cur_user, *rs_item, *rs_user, *col_ui, *col_iu;
    unsigned int* tkt;
    unsigned long long* desc;
    __half *xu_h, *xi_h, *agg_item_h, *agg_user_h, *h_item_h, *h_user_h,
           *aggH_item_h, *aggH_user_h, *w_h;
    cudaGetSymbolAddress((void**)&cnt_item, g_cnt_item);
    cudaGetSymbolAddress((void**)&cnt_user, g_cnt_user);
    cudaGetSymbolAddress((void**)&cur_item, g_cur_item);
    cudaGetSymbolAddress((void**)&cur_user, g_cur_user);
    cudaGetSymbolAddress((void**)&rs_item, g_rs_item);
    cudaGetSymbolAddress((void**)&rs_user, g_rs_user);
    cudaGetSymbolAddress((void**)&col_ui, g_col_ui);
    cudaGetSymbolAddress((void**)&col_iu, g_col_iu);
    cudaGetSymbolAddress((void**)&tkt, g_tkt);
    cudaGetSymbolAddress((void**)&desc, g_desc);
    cudaGetSymbolAddress((void**)&xu_h, g_xu_h);
    cudaGetSymbolAddress((void**)&xi_h, g_xi_h);
    cudaGetSymbolAddress((void**)&agg_item_h, g_agg_item_h);
    cudaGetSymbolAddress((void**)&agg_user_h, g_agg_user_h);
    cudaGetSymbolAddress((void**)&h_item_h, g_h_item_h);
    cudaGetSymbolAddress((void**)&h_user_h, g_h_user_h);
    cudaGetSymbolAddress((void**)&aggH_item_h, g_aggH_item_h);
    cudaGetSymbolAddress((void**)&aggH_user_h, g_aggH_user_h);
    cudaGetSymbolAddress((void**)&w_h, g_w_h);

    cudaFuncSetAttribute(gemm_h_fused<true, __half>,
                         cudaFuncAttributeMaxDynamicSharedMemorySize, HGEMM_SMEM);
    cudaFuncSetAttribute(gemm_h_fused<false, float>,
                         cudaFuncAttributeMaxDynamicSharedMemorySize, HGEMM_SMEM);

    static cudaStream_t s2 = [] {
        cudaStream_t s; cudaStreamCreateWithFlags(&s, cudaStreamNonBlocking); return s;
    }();
    static cudaStream_t s3 = [] {
        cudaStream_t s; cudaStreamCreateWithFlags(&s, cudaStreamNonBlocking); return s;
    }();
    auto mkev = [] { cudaEvent_t e; cudaEventCreateWithFlags(&e, cudaEventDisableTiming); return e; };
    static cudaEvent_t evFork  = mkev();
    static cudaEvent_t evCvt   = mkev();
    static cudaEvent_t evFillU = mkev();
    static cudaEvent_t evHuser = mkev();
    static cudaEvent_t evA2i   = mkev();
    static cudaEvent_t evDone  = mkev();

    // ---- fork ----
    cudaEventRecord(evFork, 0);
    cudaStreamWaitEvent(s2, evFork, 0);
    cudaStreamWaitEvent(s3, evFork, 0);

    // ---- s2: cvt (overlaps both CSR chains) ----
    {
        CvtArgs a;
        a.seg[0] = { x_user, xu_h, (N_USERC * DU) / 4 };
        a.seg[1] = { x_item, xi_h, (N_ITEMC * DI) / 4 };
        a.seg[2] = { W1l_ui, w_h + O_W1L_UI, (HH * DU) / 4 };
        a.seg[3] = { W1r_ui, w_h + O_W1R_UI, (HH * DI) / 4 };
        a.seg[4] = { W1l_iu, w_h + O_W1L_IU, (HH * DI) / 4 };
        a.seg[5] = { W1r_iu, w_h + O_W1R_IU, (HH * DU) / 4 };
        a.seg[6] = { W2l_ui, w_h + O_W2L_UI, (HH * HH) / 4 };
        a.seg[7] = { W2r_ui, w_h + O_W2R_UI, (HH * HH) / 4 };
        a.seg[8] = { W2l_iu, w_h + O_W2L_IU, (HH * HH) / 4 };
        a.seg[9] = { W2r_iu, w_h + O_W2R_IU, (HH * HH) / 4 };
        cvt_kernel<<<1024, 256, 0, s2>>>(a);
    }
    cudaEventRecord(evCvt, s2);

    // ---- s0: item CSR chain ----
    cudaMemsetAsync(cnt_item, 0, N_ITEMC * sizeof(int), 0);
    cudaMemsetAsync(tkt, 0, sizeof(unsigned int), 0);
    cudaMemsetAsync(desc, 0, 160 * sizeof(unsigned long long), 0);
    count_side_kernel<<<(NE / 4 + 255) / 256, 256>>>(ui_dst, cnt_item);
    scan_side_kernel<<<49, 256>>>(0);
    fill_side_kernel<<<(NE / 4 + 255) / 256, 256>>>(ui_src, ui_dst, cur_item, col_ui);

    // ---- s3: user CSR chain (fully concurrent with item CSR) ----
    cudaMemsetAsync(cnt_user, 0, N_USERC * sizeof(int), s3);
    cudaMemsetAsync(tkt + 1, 0, sizeof(unsigned int), s3);
    cudaMemsetAsync(desc + 160, 0, 160 * sizeof(unsigned long long), s3);
    count_side_kernel<<<(NE / 4 + 255) / 256, 256, 0, s3>>>(iu_dst, cnt_user);
    scan_side_kernel<<<98, 256, 0, s3>>>(1);
    fill_side_kernel<<<(NE / 4 + 255) / 256, 256, 0, s3>>>(iu_src, iu_dst, cur_user, col_iu);
    cudaEventRecord(evFillU, s3);

    // ---- s0: item layer-1 ----
    cudaStreamWaitEvent(0, evCvt, 0);
    agg_kernel<2><<<AGG_BLK_ITEM, 256>>>(xu_h, rs_item, col_ui, agg_item_h, N_ITEMC);
    {
        GemmSideH si = { agg_item_h, w_h + O_W1L_UI, xi_h, w_h + O_W1R_UI,
                         b1_ui, h_item_h, DU, DI, N_ITEMC };
        gemm_h_fused<true, __half><<<dim3(MBLK_ITEM, 2), 256, HGEMM_SMEM>>>(si, si, MBLK_ITEM);
    }

    // ---- s2: user layer-1 (after cvt; waits fill_user) ----
    cudaStreamWaitEvent(s2, evFillU, 0);
    agg_kernel<1><<<AGG_BLK_USER, 256, 0, s2>>>(xi_h, rs_user, col_iu, agg_user_h, N_USERC);
    {
        GemmSideH su = { agg_user_h, w_h + O_W1L_IU, xu_h, w_h + O_W1R_IU,
                         b1_iu, h_user_h, DI, DU, N_USERC };
        gemm_h_fused<true, __half><<<dim3(MBLK_USER, 2), 256, HGEMM_SMEM, s2>>>(su, su, MBLK_USER);
    }
    cudaEventRecord(evHuser, s2);

    float* out_user = (float*)d_out;
    float* out_item = out_user + (size_t)N_USERC * HH;

    // ---- layer 2, staggered: aggL2_item (s0) -> gemm2_item (tensor) overlaps
    //      aggL2_user (LTS) on s2 ----
    cudaStreamWaitEvent(0, evHuser, 0);
    agg_kernel<4><<<AGG_BLK_ITEM, 256>>>(h_user_h, rs_item, col_ui, aggH_item_h, N_ITEMC);
    cudaEventRecord(evA2i, 0);
    {
        GemmSideH si = { aggH_item_h, w_h + O_W2L_UI, h_item_h, w_h + O_W2R_UI,
                         b2_ui, out_item, HH, HH, N_ITEMC };
        gemm_h_fused<false, float><<<dim3(MBLK_ITEM, 2), 256, HGEMM_SMEM>>>(si, si, MBLK_ITEM);
    }

    cudaStreamWaitEvent(s2, evA2i, 0);
    agg_kernel<4><<<AGG_BLK_USER, 256, 0, s2>>>(h_item_h, rs_user, col_iu, aggH_user_h, N_USERC);
    {
        GemmSideH su = { aggH_user_h, w_h + O_W2L_IU, h_user_h, w_h + O_W2R_IU,
                         b2_iu, out_user, HH, HH, N_USERC };
        gemm_h_fused<false, float><<<dim3(MBLK_USER, 2), 256, HGEMM_SMEM, s2>>>(su, su, MBLK_USER);
    }
    cudaEventRecord(evDone, s2);

    // ---- final join back to the capture stream ----
    cudaStreamWaitEvent(0, evDone, 0);
}

// round 17
// speedup vs baseline: 1.6358x; 1.0318x over previous
#include <cuda_runtime.h>
#include <cuda_fp16.h>
#include <cstdint>

#define N_USERC 100000
#define N_ITEMC 50000
#define NE      1600000
#define DU      128
#define DI      64
#define HH      256

#define AGG_BLK_ITEM ((N_ITEMC + 7) / 8)     // 6250
#define AGG_BLK_USER ((N_USERC + 7) / 8)     // 12500
#define MBLK_ITEM ((N_ITEMC + 127) / 128)    // 391
#define MBLK_USER ((N_USERC + 127) / 128)    // 782

// ---------------- device scratch ----------------
__device__ __align__(16) int g_cnt_item[N_ITEMC];
__device__ __align__(16) int g_cnt_user[N_USERC];
__device__ __align__(16) int g_cur_item[N_ITEMC];   // seeded with rs (write cursors)
__device__ __align__(16) int g_cur_user[N_USERC];
__device__ __align__(16) int g_rs_item[N_ITEMC + 1];
__device__ __align__(16) int g_rs_user[N_USERC + 1];
__device__ __align__(16) int g_col_ui[NE];
__device__ __align__(16) int g_col_iu[NE];

__device__ unsigned int g_tkt[2];
__device__ __align__(16) unsigned long long g_desc[2][160];

__device__ __align__(128) __half g_xu_h[(size_t)N_USERC * DU];
__device__ __align__(128) __half g_xi_h[(size_t)N_ITEMC * DI];
__device__ __align__(128) __half g_agg_item_h[(size_t)N_ITEMC * DU];
__device__ __align__(128) __half g_agg_user_h[(size_t)N_USERC * DI];
__device__ __align__(128) __half g_h_item_h[(size_t)N_ITEMC * HH];
__device__ __align__(128) __half g_h_user_h[(size_t)N_USERC * HH];
__device__ __align__(128) __half g_aggH_item_h[(size_t)N_ITEMC * HH];
__device__ __align__(128) __half g_aggH_user_h[(size_t)N_USERC * HH];
__device__ __align__(128) __half g_w_h[360448];

// weight offsets in g_w_h
#define O_W1L_UI 0
#define O_W1R_UI 32768
#define O_W1L_IU 49152
#define O_W1R_IU 65536
#define O_W2L_UI 98304
#define O_W2R_UI 163840
#define O_W2L_IU 229376
#define O_W2R_IU 294912

// ---------------- fp32 -> fp16 convert ----------------
struct CvtSeg { const float* s; __half* d; int n4; };
struct CvtArgs { CvtSeg seg[10]; };

__global__ void cvt_kernel(CvtArgs args) {
    const int gid = blockIdx.x * blockDim.x + threadIdx.x;
    const int stride = gridDim.x * blockDim.x;
#pragma unroll 1
    for (int k = 0; k < 10; k++) {
        CvtSeg g = args.seg[k];
        for (int i = gid; i < g.n4; i += stride) {
            float4 v = __ldg((const float4*)g.s + i);
            __half2 h0 = __float22half2_rn(make_float2(v.x, v.y));
            __half2 h1 = __float22half2_rn(make_float2(v.z, v.w));
            uint2 o;
            o.x = *(uint32_t*)&h0;
            o.y = *(uint32_t*)&h1;
            ((uint2*)g.d)[i] = o;
        }
    }
}

// ---------------- per-side CSR build ----------------
__global__ void count_side_kernel(const int* __restrict__ dst, int* __restrict__ cnt) {
    int i = blockIdx.x * blockDim.x + threadIdx.x;
    if (i >= NE / 4) return;
    int4 a = __ldg((const int4*)dst + i);
    atomicAdd(&cnt[a.x], 1); atomicAdd(&cnt[a.y], 1);
    atomicAdd(&cnt[a.z], 1); atomicAdd(&cnt[a.w], 1);
}

// per-side decoupled-lookback scan; seeds cur with rs
__global__ void scan_side_kernel(int y) {
    const int* __restrict__ cnt = y == 0 ? g_cnt_item : g_cnt_user;
    int* __restrict__ rs  = y == 0 ? g_rs_item  : g_rs_user;
    int* __restrict__ cur = y == 0 ? g_cur_item : g_cur_user;
    const int n = y == 0 ? N_ITEMC : N_USERC;
    const int nblk = (n + 1023) / 1024;
    if ((int)blockIdx.x >= nblk) return;

    __shared__ int s_vb;
    __shared__ int s_wsum[8];
    __shared__ int s_run;
    const int tid = threadIdx.x, lane = tid & 31, wid = tid >> 5;

    if (tid == 0) s_vb = atomicAdd(&g_tkt[y], 1u);
    __syncthreads();
    const int vb = s_vb;
    const int base = vb * 1024 + tid * 4;

    int v0 = 0, v1 = 0, v2 = 0, v3 = 0;
    if (base + 3 < n) {
        v0 = cnt[base]; v1 = cnt[base + 1]; v2 = cnt[base + 2]; v3 = cnt[base + 3];
    } else {
        if (base     < n) v0 = cnt[base];
        if (base + 1 < n) v1 = cnt[base + 1];
        if (base + 2 < n) v2 = cnt[base + 2];
        if (base + 3 < n) v3 = cnt[base + 3];
    }
    const int tot = v0 + v1 + v2 + v3;
    int inc = tot;
#pragma unroll
    for (int o = 1; o < 32; o <<= 1) {
        int u = __shfl_up_sync(0xffffffffu, inc, o);
        if (lane >= o) inc += u;
    }
    if (lane == 31) s_wsum[wid] = inc;
    __syncthreads();
    if (wid == 0) {
        int w = (lane < 8) ? s_wsum[lane] : 0;
#pragma unroll
        for (int o = 1; o < 8; o <<= 1) {
            int u = __shfl_up_sync(0xffffffffu, w, o);
            if (lane >= o) w += u;
        }
        if (lane < 8) s_wsum[lane] = w;
    }
    __syncthreads();
    const int agg = s_wsum[7];
    const int thr_exc = (wid ? s_wsum[wid - 1] : 0) + inc - tot;

    if (tid == 0) {
        if (vb == 0) {
            atomicExch(&g_desc[y][0], (2ull << 32) | (unsigned)agg);
            s_run = 0;
        } else {
            atomicExch(&g_desc[y][vb], (1ull << 32) | (unsigned)agg);
            int run = 0, p = vb - 1;
            while (true) {
                unsigned long long d;
                do { d = atomicAdd(&g_desc[y][p], 0ull); } while ((d >> 32) == 0ull);
                run += (int)(d & 0xffffffffull);
                if ((d >> 32) == 2ull) break;
                p--;
            }
            atomicExch(&g_desc[y][vb], (2ull << 32) | (unsigned)(run + agg));
            s_run = run;
        }
    }
    __syncthreads();
    const int run = s_run;
    const int e0 = run + thr_exc;
    if (base     < n) { int v = e0;                rs[base]     = v; cur[base]     = v; }
    if (base + 1 < n) { int v = e0 + v0;           rs[base + 1] = v; cur[base + 1] = v; }
    if (base + 2 < n) { int v = e0 + v0 + v1;      rs[base + 2] = v; cur[base + 2] = v; }
    if (base + 3 < n) { int v = e0 + v0 + v1 + v2; rs[base + 3] = v; cur[base + 3] = v; }
    if (vb == nblk - 1 && tid == 0) rs[n] = run + agg;
}

// per-side fill: single atomic per edge (cursor pre-seeded with row start)
__global__ void fill_side_kernel(const int* __restrict__ src, const int* __restrict__ dst,
                                 int* __restrict__ cur, int* __restrict__ col) {
    int i = blockIdx.x * blockDim.x + threadIdx.x;
    if (i >= NE / 4) return;
    int4 s4 = __ldg((const int4*)src + i);
    int4 d4 = __ldg((const int4*)dst + i);
    int p0 = atomicAdd(&cur[d4.x], 1);
    int p1 = atomicAdd(&cur[d4.y], 1);
    int p2 = atomicAdd(&cur[d4.z], 1);
    int p3 = atomicAdd(&cur[d4.w], 1);
    col[p0] = s4.x;
    col[p1] = s4.y;
    col[p2] = s4.z;
    col[p3] = s4.w;
}

// ---------------- fp16 gather-based segment mean ----------------
// Pairwise fp16 pre-reduction: rows (0,1) and (2,3) are summed with one HADD2
// per word before fp32 conversion — each value passes through at most ONE
// fp16 addition, then everything is fp32. Cuts hot-loop instructions ~37%.
template <int HV>
__device__ __forceinline__ void ld_row(const __half* p, int lane, uint32_t* raw) {
    if constexpr (HV == 4) {
        uint4 t = __ldg((const uint4*)p + lane);
        raw[0] = t.x; raw[1] = t.y; raw[2] = t.z; raw[3] = t.w;
    } else if constexpr (HV == 2) {
        uint2 t = __ldg((const uint2*)p + lane);
        raw[0] = t.x; raw[1] = t.y;
    } else {
        raw[0] = __ldg((const uint32_t*)p + lane);
    }
}

template <int HV>
__device__ __forceinline__ void agg_body_h(const __half* __restrict__ X,
                                           const int* __restrict__ rs,
                                           const int* __restrict__ col,
                                           __half* __restrict__ out, int w, int lane) {
    const int F = HV * 64;
    int s = rs[w], e = rs[w + 1];
    float2 acc[2][HV];
#pragma unroll
    for (int u = 0; u < 2; u++)
#pragma unroll
        for (int v = 0; v < HV; v++) acc[u][v] = make_float2(0.f, 0.f);

    int j = s;
    for (; j + 3 < e; j += 4) {
        uint32_t raw[4][HV];
#pragma unroll
        for (int u = 0; u < 4; u++)
            ld_row<HV>(X + (size_t)col[j + u] * F, lane, raw[u]);
#pragma unroll
        for (int v = 0; v < HV; v++) {
            __half2 p01 = __hadd2(*(__half2*)&raw[0][v], *(__half2*)&raw[1][v]);
            __half2 p23 = __hadd2(*(__half2*)&raw[2][v], *(__half2*)&raw[3][v]);
            float2 f0 = __half22float2(p01);
            float2 f1 = __half22float2(p23);
            acc[0][v].x += f0.x; acc[0][v].y += f0.y;
            acc[1][v].x += f1.x; acc[1][v].y += f1.y;
        }
    }
    for (; j < e; j++) {
        uint32_t raw[HV];
        ld_row<HV>(X + (size_t)col[j] * F, lane, raw);
#pragma unroll
        for (int v = 0; v < HV; v++) {
            float2 f = __half22float2(*(__half2*)&raw[v]);
            acc[0][v].x += f.x; acc[0][v].y += f.y;
        }
    }
    float inv = (e > s) ? 1.0f / (float)(e - s) : 0.0f;
    uint32_t o[HV];
#pragma unroll
    for (int v = 0; v < HV; v++) {
        float2 m;
        m.x = (acc[0][v].x + acc[1][v].x) * inv;
        m.y = (acc[0][v].y + acc[1][v].y) * inv;
        __half2 h = __float22half2_rn(m);
        o[v] = *(uint32_t*)&h;
    }
    __half* orow = out + (size_t)w * F;
    if constexpr (HV == 4) ((uint4*)orow)[lane] = make_uint4(o[0], o[1], o[2], o[3]);
    else if constexpr (HV == 2) ((uint2*)orow)[lane] = make_uint2(o[0], o[1]);
    else ((uint32_t*)orow)[lane] = o[0];
}

template <int HV>
__global__ __launch_bounds__(256) void agg_kernel(const __half* __restrict__ X,
                                                  const int* __restrict__ rs,
                                                  const int* __restrict__ col,
                                                  __half* __restrict__ out, int ndst) {
    int w = blockIdx.x * 8 + (threadIdx.x >> 5);
    int lane = threadIdx.x & 31;
    if (w < ndst) agg_body_h<HV>(X, rs, col, out, w, lane);
}

// ================= fp16 mma.sync dual-A GEMM, cp.async 3-stage =================
#define HROW_B    80
#define HSTAGE_A  (128 * HROW_B)           // 10240
#define HSTAGE    (2 * HSTAGE_A)           // 20480
#define NSTAGE    3
#define HGEMM_SMEM (NSTAGE * HSTAGE)       // 61440

struct GemmSideH {
    const __half *A1, *W1, *A2, *W2;
    const float* bias;
    void* C;
    int K1, K2, M;
};

__device__ __forceinline__ uint32_t smem_u32(const void* p) {
    uint32_t a;
    asm("{ .reg .u64 t; cvta.to.shared.u64 t, %1; cvt.u32.u64 %0, t; }" : "=r"(a) : "l"(p));
    return a;
}

__device__ __forceinline__ void ldsm_x4(uint32_t* r, uint32_t addr) {
    asm volatile("ldmatrix.sync.aligned.m8n8.x4.shared.b16 {%0,%1,%2,%3}, [%4];"
                 : "=r"(r[0]), "=r"(r[1]), "=r"(r[2]), "=r"(r[3]) : "r"(addr));
}

__device__ __forceinline__ void mma_f16(float* d, const uint32_t* a, uint32_t b0, uint32_t b1) {
    asm volatile(
        "mma.sync.aligned.m16n8k16.row.col.f32.f16.f16.f32 "
        "{%0,%1,%2,%3}, {%4,%5,%6,%7}, {%8,%9}, {%0,%1,%2,%3};"
        : "+f"(d[0]), "+f"(d[1]), "+f"(d[2]), "+f"(d[3])
        : "r"(a[0]), "r"(a[1]), "r"(a[2]), "r"(a[3]), "r"(b0), "r"(b1));
}

__device__ __forceinline__ void cp_async16(uint32_t smem, const void* g, bool pred) {
    int sz = pred ? 16 : 0;
    asm volatile("cp.async.cg.shared.global [%0], [%1], 16, %2;"
                 :: "r"(smem), "l"(g), "r"(sz) : "memory");
}
#define CP_COMMIT() asm volatile("cp.async.commit_group;" ::: "memory")
#define CP_WAIT1()  asm volatile("cp.async.wait_group 1;" ::: "memory")

template <bool RELU, typename CT>
__global__ __launch_bounds__(256, 2) void gemm_h_fused(GemmSideH sa, GemmSideH sb, int mblk_a) {
    extern __shared__ __align__(16) char dsmem[];
    const uint32_t sm0 = smem_u32(dsmem);

    const bool sideA = (int)blockIdx.x < mblk_a;
    const __half* A1 = sideA ? sa.A1 : sb.A1;
    const __half* W1 = sideA ? sa.W1 : sb.W1;
    const __half* A2 = sideA ? sa.A2 : sb.A2;
    const __half* W2 = sideA ? sa.W2 : sb.W2;
    const float* bias = sideA ? sa.bias : sb.bias;
    CT* C = (CT*)(sideA ? sa.C : sb.C);
    const int K1 = sideA ? sa.K1 : sb.K1;
    const int K2 = sideA ? sa.K2 : sb.K2;
    const int M  = sideA ? sa.M  : sb.M;
    const int mb = sideA ? blockIdx.x : blockIdx.x - mblk_a;

    const int tid = threadIdx.x;
    const int wid = tid >> 5;
    const int lane = tid & 31;
    const int warp_m = wid >> 2;
    const int warp_n = wid & 3;
    const int m0 = mb * 128;
    const int n0 = blockIdx.y * 128;

    const int row0 = tid >> 2;
    const int cc8 = (tid & 3) * 8;
    const uint32_t stoff = (uint32_t)(row0 * HROW_B + (tid & 3) * 16);

    float acc[4][4][4];
#pragma unroll
    for (int i = 0; i < 4; i++)
#pragma unroll
        for (int j = 0; j < 4; j++)
#pragma unroll
            for (int k = 0; k < 4; k++) acc[i][j][k] = 0.f;

    const int n1 = K1 / 32;
    const int n2 = K2 / 32;
    const int T = n1 + n2;

    auto issue_g = [&](int it, int slot) {
        const __half* A; const __half* W; int K, k0;
        if (it < n1) { A = A1; W = W1; K = K1; k0 = it * 32; }
        else         { A = A2; W = W2; K = K2; k0 = (it - n1) * 32; }
        const int cc = k0 + cc8;
        const uint32_t bA = sm0 + slot * HSTAGE;
        const uint32_t bB = bA + HSTAGE_A;
#pragma unroll
        for (int q = 0; q < 2; q++) {
            const int r = row0 + 64 * q;
            cp_async16(bA + stoff + (uint32_t)(64 * q * HROW_B),
                       A + (size_t)(m0 + r) * K + cc, m0 + r < M);
            cp_async16(bB + stoff + (uint32_t)(64 * q * HROW_B),
                       W + (size_t)(n0 + r) * K + cc, true);
        }
    };

    const int rowsel = (lane & 7) | (((lane >> 3) & 1) << 3);
    const int colsel = (lane >> 4) * 16;

    auto compute_s = [&](int st) {
        const uint32_t bA = sm0 + st * HSTAGE;
        const uint32_t bB = bA + HSTAGE_A;
        const uint32_t aBase = bA + (uint32_t)((warp_m * 64 + rowsel) * HROW_B + colsel);
        const uint32_t bBase = bB + (uint32_t)((warp_n * 32 + rowsel) * HROW_B + colsel);
#pragma unroll
        for (int ks = 0; ks < 2; ks++) {
            const uint32_t ko = ks * 32;
            uint32_t af[4][4], bf[8];
#pragma unroll
            for (int i = 0; i < 4; i++)
                ldsm_x4(af[i], aBase + i * (16 * HROW_B) + ko);
            ldsm_x4(bf + 0, bBase + ko);
            ldsm_x4(bf + 4, bBase + 16 * HROW_B + ko);
#pragma unroll
            for (int i = 0; i < 4; i++)
#pragma unroll
                for (int j = 0; j < 4; j++) {
                    const int bi = (j >> 1) * 4 + (j & 1);
                    mma_f16(acc[i][j], af[i], bf[bi], bf[bi + 2]);
                }
        }
    };

    issue_g(0, 0);
    CP_COMMIT();
    if (T > 1) issue_g(1, 1);
    CP_COMMIT();
    CP_WAIT1();
    __syncthreads();

    int slot = 0;
#pragma unroll 1
    for (int it = 0; it < T; it++) {
        compute_s(slot);
        if (it + 2 < T) issue_g(it + 2, (it + 2) % NSTAGE);
        CP_COMMIT();
        CP_WAIT1();
        __syncthreads();
        slot = (slot + 1 == NSTAGE) ? 0 : slot + 1;
    }

    const int g = lane >> 2;
    const int t = lane & 3;
#pragma unroll
    for (int j = 0; j < 4; j++) {
        const int nb = n0 + warp_n * 32 + j * 8 + t * 2;
        const float bx = bias[nb], by = bias[nb + 1];
#pragma unroll
        for (int i = 0; i < 4; i++) {
            const int rlo = m0 + warp_m * 64 + i * 16 + g;
            if (rlo < M) {
                float vx = acc[i][j][0] + bx, vy = acc[i][j][1] + by;
                if (RELU) { vx = fmaxf(vx, 0.f); vy = fmaxf(vy, 0.f); }
                if constexpr (sizeof(CT) == 2) {
                    __half2 hv = __float22half2_rn(make_float2(vx, vy));
                    *(__half2*)((__half*)C + (size_t)rlo * HH + nb) = hv;
                } else {
                    *(float2*)((float*)C + (size_t)rlo * HH + nb) = make_float2(vx, vy);
                }
            }
            const int rhi = rlo + 8;
            if (rhi < M) {
                float vx = acc[i][j][2] + bx, vy = acc[i][j][3] + by;
                if (RELU) { vx = fmaxf(vx, 0.f); vy = fmaxf(vy, 0.f); }
                if constexpr (sizeof(CT) == 2) {
                    __half2 hv = __float22half2_rn(make_float2(vx, vy));
                    *(__half2*)((__half*)C + (size_t)rhi * HH + nb) = hv;
                } else {
                    *(float2*)((float*)C + (size_t)rhi * HH + nb) = make_float2(vx, vy);
                }
            }
        }
    }
}

// ---------------- host ----------------
extern "C" void kernel_launch(void* const* d_in, const int* in_sizes, int n_in,
                              void* d_out, int out_size) {
    const float* x_user = (const float*)d_in[0];
    const float* x_item = (const float*)d_in[1];
    const int* ui_src = (const int*)d_in[2];
    const int* ui_dst = (const int*)d_in[3];
    const int* iu_src = (const int*)d_in[4];
    const int* iu_dst = (const int*)d_in[5];
    const float* W1l_ui = (const float*)d_in[6];
    const float* b1_ui  = (const float*)d_in[7];
    const float* W1r_ui = (const float*)d_in[8];
    const float* W1l_iu = (const float*)d_in[9];
    const float* b1_iu  = (const float*)d_in[10];
    const float* W1r_iu = (const float*)d_in[11];
    const float* W2l_ui = (const float*)d_in[12];
    const float* b2_ui  = (const float*)d_in[13];
    const float* W2r_ui = (const float*)d_in[14];
    const float* W2l_iu = (const float*)d_in[15];
    const float* b2_iu  = (const float*)d_in[16];
    const float* W2r_iu = (const float*)d_in[17];

    int *cnt_item, *cnt_user, *cur_item, *cur_user, *rs_item, *rs_user, *col_ui, *col_iu;
    unsigned int* tkt;
    unsigned long long* desc;
    __half *xu_h, *xi_h, *agg_item_h, *agg_user_h, *h_item_h, *h_user_h,
           *aggH_item_h, *aggH_user_h, *w_h;
    cudaGetSymbolAddress((void**)&cnt_item, g_cnt_item);
    cudaGetSymbolAddress((void**)&cnt_user, g_cnt_user);
    cudaGetSymbolAddress((void**)&cur_item, g_cur_item);
    cudaGetSymbolAddress((void**)&cur_user, g_cur_user);
    cudaGetSymbolAddress((void**)&rs_item, g_rs_item);
    cudaGetSymbolAddress((void**)&rs_user, g_rs_user);
    cudaGetSymbolAddress((void**)&col_ui, g_col_ui);
    cudaGetSymbolAddress((void**)&col_iu, g_col_iu);
    cudaGetSymbolAddress((void**)&tkt, g_tkt);
    cudaGetSymbolAddress((void**)&desc, g_desc);
    cudaGetSymbolAddress((void**)&xu_h, g_xu_h);
    cudaGetSymbolAddress((void**)&xi_h, g_xi_h);
    cudaGetSymbolAddress((void**)&agg_item_h, g_agg_item_h);
    cudaGetSymbolAddress((void**)&agg_user_h, g_agg_user_h);
    cudaGetSymbolAddress((void**)&h_item_h, g_h_item_h);
    cudaGetSymbolAddress((void**)&h_user_h, g_h_user_h);
    cudaGetSymbolAddress((void**)&aggH_item_h, g_aggH_item_h);
    cudaGetSymbolAddress((void**)&aggH_user_h, g_aggH_user_h);
    cudaGetSymbolAddress((void**)&w_h, g_w_h);

    cudaFuncSetAttribute(gemm_h_fused<true, __half>,
                         cudaFuncAttributeMaxDynamicSharedMemorySize, HGEMM_SMEM);
    cudaFuncSetAttribute(gemm_h_fused<false, float>,
                         cudaFuncAttributeMaxDynamicSharedMemorySize, HGEMM_SMEM);

    static cudaStream_t s2 = [] {
        cudaStream_t s; cudaStreamCreateWithFlags(&s, cudaStreamNonBlocking); return s;
    }();
    static cudaStream_t s3 = [] {
        cudaStream_t s; cudaStreamCreateWithFlags(&s, cudaStreamNonBlocking); return s;
    }();
    auto mkev = [] { cudaEvent_t e; cudaEventCreateWithFlags(&e, cudaEventDisableTiming); return e; };
    static cudaEvent_t evFork  = mkev();
    static cudaEvent_t evCvt   = mkev();
    static cudaEvent_t evFillU = mkev();
    static cudaEvent_t evHuser = mkev();
    static cudaEvent_t evA2i   = mkev();
    static cudaEvent_t evDone  = mkev();

    // ---- fork ----
    cudaEventRecord(evFork, 0);
    cudaStreamWaitEvent(s2, evFork, 0);
    cudaStreamWaitEvent(s3, evFork, 0);

    // ---- s2: cvt (overlaps both CSR chains) ----
    {
        CvtArgs a;
        a.seg[0] = { x_user, xu_h, (N_USERC * DU) / 4 };
        a.seg[1] = { x_item, xi_h, (N_ITEMC * DI) / 4 };
        a.seg[2] = { W1l_ui, w_h + O_W1L_UI, (HH * DU) / 4 };
        a.seg[3] = { W1r_ui, w_h + O_W1R_UI, (HH * DI) / 4 };
        a.seg[4] = { W1l_iu, w_h + O_W1L_IU, (HH * DI) / 4 };
        a.seg[5] = { W1r_iu, w_h + O_W1R_IU, (HH * DU) / 4 };
        a.seg[6] = { W2l_ui, w_h + O_W2L_UI, (HH * HH) / 4 };
        a.seg[7] = { W2r_ui, w_h + O_W2R_UI, (HH * HH) / 4 };
        a.seg[8] = { W2l_iu, w_h + O_W2L_IU, (HH * HH) / 4 };
        a.seg[9] = { W2r_iu, w_h + O_W2R_IU, (HH * HH) / 4 };
        cvt_kernel<<<1024, 256, 0, s2>>>(a);
    }
    cudaEventRecord(evCvt, s2);

    // ---- s0: item CSR chain ----
    cudaMemsetAsync(cnt_item, 0, N_ITEMC * sizeof(int), 0);
    cudaMemsetAsync(tkt, 0, sizeof(unsigned int), 0);
    cudaMemsetAsync(desc, 0, 160 * sizeof(unsigned long long), 0);
    count_side_kernel<<<(NE / 4 + 255) / 256, 256>>>(ui_dst, cnt_item);
    scan_side_kernel<<<49, 256>>>(0);
    fill_side_kernel<<<(NE / 4 + 255) / 256, 256>>>(ui_src, ui_dst, cur_item, col_ui);

    // ---- s3: user CSR chain (fully concurrent with item CSR) ----
    cudaMemsetAsync(cnt_user, 0, N_USERC * sizeof(int), s3);
    cudaMemsetAsync(tkt + 1, 0, sizeof(unsigned int), s3);
    cudaMemsetAsync(desc + 160, 0, 160 * sizeof(unsigned long long), s3);
    count_side_kernel<<<(NE / 4 + 255) / 256, 256, 0, s3>>>(iu_dst, cnt_user);
    scan_side_kernel<<<98, 256, 0, s3>>>(1);
    fill_side_kernel<<<(NE / 4 + 255) / 256, 256, 0, s3>>>(iu_src, iu_dst, cur_user, col_iu);
    cudaEventRecord(evFillU, s3);

    // ---- s0: item layer-1 ----
    cudaStreamWaitEvent(0, evCvt, 0);
    agg_kernel<2><<<AGG_BLK_ITEM, 256>>>(xu_h, rs_item, col_ui, agg_item_h, N_ITEMC);
    {
        GemmSideH si = { agg_item_h, w_h + O_W1L_UI, xi_h, w_h + O_W1R_UI,
                         b1_ui, h_item_h, DU, DI, N_ITEMC };
        gemm_h_fused<true, __half><<<dim3(MBLK_ITEM, 2), 256, HGEMM_SMEM>>>(si, si, MBLK_ITEM);
    }

    // ---- s2: user layer-1 (after cvt; waits fill_user) ----
    cudaStreamWaitEvent(s2, evFillU, 0);
    agg_kernel<1><<<AGG_BLK_USER, 256, 0, s2>>>(xi_h, rs_user, col_iu, agg_user_h, N_USERC);
    {
        GemmSideH su = { agg_user_h, w_h + O_W1L_IU, xu_h, w_h + O_W1R_IU,
                         b1_iu, h_user_h, DI, DU, N_USERC };
        gemm_h_fused<true, __half><<<dim3(MBLK_USER, 2), 256, HGEMM_SMEM, s2>>>(su, su, MBLK_USER);
    }
    cudaEventRecord(evHuser, s2);

    float* out_user = (float*)d_out;
    float* out_item = out_user + (size_t)N_USERC * HH;

    // ---- layer 2, staggered: aggL2_item (s0) -> gemm2_item (tensor) overlaps
    //      aggL2_user (LTS) on s2 ----
    cudaStreamWaitEvent(0, evHuser, 0);
    agg_kernel<4><<<AGG_BLK_ITEM, 256>>>(h_user_h, rs_item, col_ui, aggH_item_h, N_ITEMC);
    cudaEventRecord(evA2i, 0);
    {
        GemmSideH si = { aggH_item_h, w_h + O_W2L_UI, h_item_h, w_h + O_W2R_UI,
                         b2_ui, out_item, HH, HH, N_ITEMC };
        gemm_h_fused<false, float><<<dim3(MBLK_ITEM, 2), 256, HGEMM_SMEM>>>(si, si, MBLK_ITEM);
    }

    cudaStreamWaitEvent(s2, evA2i, 0);
    agg_kernel<4><<<AGG_BLK_USER, 256, 0, s2>>>(h_item_h, rs_user, col_iu, aggH_user_h, N_USERC);
    {
        GemmSideH su = { aggH_user_h, w_h + O_W2L_IU, h_user_h, w_h + O_W2R_IU,
                         b2_iu, out_user, HH, HH, N_USERC };
        gemm_h_fused<false, float><<<dim3(MBLK_USER, 2), 256, HGEMM_SMEM, s2>>>(su, su, MBLK_USER);
    }
    cudaEventRecord(evDone, s2);

    // ---- final join back to the capture stream ----
    cudaStreamWaitEvent(0, evDone, 0);
}